// round 2
// baseline (speedup 1.0000x reference)
#include <cuda_runtime.h>
#include <math.h>

#define LAYERS 2
#define DMODEL 1024
#define NHEAD 16
#define HDIM 64
#define FFDIM 4096
#define NEXP 8
#define SEQ 1024
#define BATCH 8
#define NTOK (SEQ*BATCH)          // 8192
#define LNEPS 1e-5f

// ---------------- persistent scratch (no allocations allowed) ----------------
__device__ float g_X[(size_t)NTOK*DMODEL];
__device__ float g_QKin[(size_t)NTOK*DMODEL];
__device__ float g_QK[(size_t)NTOK*2*DMODEL];
__device__ float g_V[(size_t)NTOK*DMODEL];
__device__ float g_O[(size_t)NTOK*DMODEL];
__device__ float g_Attn[(size_t)NTOK*DMODEL];
__device__ float g_Moe[(size_t)NTOK*DMODEL];
__device__ float g_H[(size_t)2*NTOK*FFDIM];       // 256 MB expert hidden
__device__ int   g_topi[NTOK*2];
__device__ float g_topp[NTOK*2];
__device__ int   g_counts[NEXP];
__device__ int   g_segoff[NEXP];
__device__ int   g_cursor[NEXP];
__device__ int   g_tokidx[2*NTOK];
__device__ float g_tokprob[2*NTOK];
__device__ float g_usage[LAYERS*NEXP];

// ---------------- elementwise helpers ----------------
__global__ void copy_k(const float* __restrict__ a, float* __restrict__ o, size_t n) {
    size_t i = (size_t)blockIdx.x*blockDim.x + threadIdx.x;
    size_t st = (size_t)gridDim.x*blockDim.x;
    for (; i < n; i += st) o[i] = a[i];
}
__global__ void add_k(const float* __restrict__ a, const float* __restrict__ b,
                      float* __restrict__ o, size_t n) {
    size_t i = (size_t)blockIdx.x*blockDim.x + threadIdx.x;
    size_t st = (size_t)gridDim.x*blockDim.x;
    for (; i < n; i += st) o[i] = a[i] + b[i];
}
__global__ void zero_k(float* __restrict__ p, size_t n, int* a, int* b, int nc) {
    size_t i = (size_t)blockIdx.x*blockDim.x + threadIdx.x;
    size_t st = (size_t)gridDim.x*blockDim.x;
    for (; i < n; i += st) p[i] = 0.f;
    if (blockIdx.x == 0 && (int)threadIdx.x < nc) {
        if (a) a[threadIdx.x] = 0;
        if (b) b[threadIdx.x] = 0;
    }
}

// ---------------- generic SGEMM: C[M,N] = A[M,K] * B[N,K]^T + bias ----------------
// Register-prefetch pipelined: k-tile i+1 global loads are issued BEFORE the
// FMA block of tile i, so the ~250-600cyc load latency drains behind ~512cyc
// of compute instead of being exposed at each k-step.
// MODE 0: dense in/out.
// MODE 1: expert FF1. blockIdx.z = e. M=counts[e]. A rows gathered via tokidx.
//         C row = segoff[e]+row. ReLU.
// MODE 2: expert FF2. A rows = segoff[e]+row (contiguous h). Epilogue:
//         atomicAdd(scat[tok*ldc+n], prob*(acc+bias)).
template<int MODE>
__global__ __launch_bounds__(256) void gemm_k(
    const float* __restrict__ A, int lda,
    const float* __restrict__ Bw, int ldb,
    const float* __restrict__ bias,
    float* __restrict__ C, int ldc,
    int M, int N, int Kd,
    const int* __restrict__ tokidx, const float* __restrict__ tokprob,
    const int* __restrict__ segoff, const int* __restrict__ counts,
    size_t w_stride, int b_stride,
    float* __restrict__ scat)
{
    int base = 0;
    if (MODE != 0) {
        int e = blockIdx.z;
        base = segoff[e];
        M = counts[e];
        Bw  += (size_t)e * w_stride;
        bias += (size_t)e * b_stride;
    }
    int m0 = blockIdx.y * 128;
    if (m0 >= M) return;
    int n0 = blockIdx.x * 128;

    __shared__ float As[16][132];
    __shared__ float Bs[16][132];

    int tid  = threadIdx.x;
    int tcol = tid & 15;
    int trow = tid >> 4;

    float acc[8][8];
    #pragma unroll
    for (int i = 0; i < 8; i++)
        #pragma unroll
        for (int j = 0; j < 8; j++) acc[i][j] = 0.f;

    int rA0 = tid >> 2;          // 0..63
    int rA1 = rA0 + 64;          // 64..127
    int kc  = (tid & 3) * 4;

    bool v0 = (m0 + rA0) < M;
    bool v1 = (m0 + rA1) < M;
    size_t arow0, arow1;
    if (MODE == 1) {
        arow0 = v0 ? (size_t)tokidx[base + m0 + rA0] : 0;
        arow1 = v1 ? (size_t)tokidx[base + m0 + rA1] : 0;
    } else if (MODE == 2) {
        arow0 = (size_t)(base + m0 + rA0);
        arow1 = (size_t)(base + m0 + rA1);
    } else {
        arow0 = (size_t)(m0 + rA0);
        arow1 = (size_t)(m0 + rA1);
    }
    const float* Ap0 = A + arow0 * (size_t)lda + kc;
    const float* Ap1 = A + arow1 * (size_t)lda + kc;
    const float* Bp0 = Bw + (size_t)(n0 + rA0) * ldb + kc;
    const float* Bp1 = Bw + (size_t)(n0 + rA1) * ldb + kc;

    // prologue: load k-tile 0 into registers
    float4 a0 = v0 ? *(const float4*)(Ap0) : make_float4(0.f,0.f,0.f,0.f);
    float4 a1 = v1 ? *(const float4*)(Ap1) : make_float4(0.f,0.f,0.f,0.f);
    float4 b0 = *(const float4*)(Bp0);
    float4 b1 = *(const float4*)(Bp1);

    for (int k0 = 0; k0 < Kd; k0 += 16) {
        // store current tile to smem
        As[kc+0][rA0]=a0.x; As[kc+1][rA0]=a0.y; As[kc+2][rA0]=a0.z; As[kc+3][rA0]=a0.w;
        As[kc+0][rA1]=a1.x; As[kc+1][rA1]=a1.y; As[kc+2][rA1]=a1.z; As[kc+3][rA1]=a1.w;
        Bs[kc+0][rA0]=b0.x; Bs[kc+1][rA0]=b0.y; Bs[kc+2][rA0]=b0.z; Bs[kc+3][rA0]=b0.w;
        Bs[kc+0][rA1]=b1.x; Bs[kc+1][rA1]=b1.y; Bs[kc+2][rA1]=b1.z; Bs[kc+3][rA1]=b1.w;
        __syncthreads();

        // prefetch next tile (latency hidden under FMA block below)
        int kn = k0 + 16;
        if (kn < Kd) {
            a0 = v0 ? *(const float4*)(Ap0 + kn) : make_float4(0.f,0.f,0.f,0.f);
            a1 = v1 ? *(const float4*)(Ap1 + kn) : make_float4(0.f,0.f,0.f,0.f);
            b0 = *(const float4*)(Bp0 + kn);
            b1 = *(const float4*)(Bp1 + kn);
        }

        #pragma unroll
        for (int kk = 0; kk < 16; kk++) {
            float a[8], b[8];
            *(float4*)(a)   = *(const float4*)(&As[kk][trow*8]);
            *(float4*)(a+4) = *(const float4*)(&As[kk][trow*8+4]);
            *(float4*)(b)   = *(const float4*)(&Bs[kk][tcol*8]);
            *(float4*)(b+4) = *(const float4*)(&Bs[kk][tcol*8+4]);
            #pragma unroll
            for (int i = 0; i < 8; i++)
                #pragma unroll
                for (int j = 0; j < 8; j++)
                    acc[i][j] += a[i]*b[j];
        }
        __syncthreads();
    }

    int rbase = m0 + trow*8;
    int cbase = n0 + tcol*8;
    if (MODE == 0) {
        #pragma unroll
        for (int i = 0; i < 8; i++) {
            int r = rbase + i;
            if (r < M) {
                float* crow = C + (size_t)r*ldc + cbase;
                #pragma unroll
                for (int j = 0; j < 8; j++) crow[j] = acc[i][j] + bias[cbase+j];
            }
        }
    } else if (MODE == 1) {
        #pragma unroll
        for (int i = 0; i < 8; i++) {
            int r = rbase + i;
            if (r < M) {
                float* crow = C + (size_t)(base + r)*ldc + cbase;
                #pragma unroll
                for (int j = 0; j < 8; j++) {
                    float v = acc[i][j] + bias[cbase+j];
                    crow[j] = v > 0.f ? v : 0.f;
                }
            }
        }
    } else {
        #pragma unroll
        for (int i = 0; i < 8; i++) {
            int r = rbase + i;
            if (r < M) {
                int   t = tokidx[base + r];
                float p = tokprob[base + r];
                float* orow = scat + (size_t)t*ldc + cbase;
                #pragma unroll
                for (int j = 0; j < 8; j++)
                    atomicAdd(&orow[j], p * (acc[i][j] + bias[cbase+j]));
            }
        }
    }
}

// ---------------- flash attention: per (b,h), 64 q-rows/block, kv tiles of 64 ----------------
#define SP 65
#define FLASH_SMEM ((4*64*SP + 64*17) * 4)

__global__ __launch_bounds__(256) void flash_k(const float* __restrict__ QK,
                                               const float* __restrict__ V,
                                               float* __restrict__ O)
{
    extern __shared__ float sm[];
    float* Qs  = sm;
    float* Ks  = Qs + 64*SP;
    float* Vs  = Ks + 64*SP;
    float* Ps  = Vs + 64*SP;
    float* red = Ps + 64*SP;   // 64 x 17

    int tid = threadIdx.x;
    int tx = tid & 15, ty = tid >> 4;
    int bh = blockIdx.y;
    int b  = bh >> 4;
    int h  = bh & 15;
    int s0 = blockIdx.x * 64;

    // load Q tile (rows 0..63 of this q-block, head slice)
    #pragma unroll
    for (int i = 0; i < 4; i++) {
        int r = ty + i*16;
        int d = tx * 4;
        float4 q = *(const float4*)(QK + ((size_t)((s0+r)*BATCH + b))*2048 + h*64 + d);
        Qs[r*SP + d]   = q.x; Qs[r*SP + d+1] = q.y;
        Qs[r*SP + d+2] = q.z; Qs[r*SP + d+3] = q.w;
    }

    float m_i[4], l_i[4], o_acc[4][4];
    #pragma unroll
    for (int i = 0; i < 4; i++) {
        m_i[i] = -1e30f; l_i[i] = 0.f;
        #pragma unroll
        for (int j = 0; j < 4; j++) o_acc[i][j] = 0.f;
    }
    const float scale = 0.125f;   // 1/sqrt(64)

    for (int t0 = 0; t0 < SEQ; t0 += 64) {
        __syncthreads();
        #pragma unroll
        for (int i = 0; i < 4; i++) {
            int r = ty + i*16;
            int d = tx * 4;
            size_t tok = (size_t)((t0+r)*BATCH + b);
            float4 kv = *(const float4*)(QK + tok*2048 + DMODEL + h*64 + d);
            Ks[r*SP + d]   = kv.x; Ks[r*SP + d+1] = kv.y;
            Ks[r*SP + d+2] = kv.z; Ks[r*SP + d+3] = kv.w;
            float4 vv = *(const float4*)(V + tok*DMODEL + h*64 + d);
            Vs[r*SP + d]   = vv.x; Vs[r*SP + d+1] = vv.y;
            Vs[r*SP + d+2] = vv.z; Vs[r*SP + d+3] = vv.w;
        }
        __syncthreads();

        float s[4][4];
        #pragma unroll
        for (int i = 0; i < 4; i++)
            #pragma unroll
            for (int j = 0; j < 4; j++) s[i][j] = 0.f;
        for (int d = 0; d < 64; d++) {
            float a0 = Qs[(ty*4+0)*SP + d], a1 = Qs[(ty*4+1)*SP + d];
            float a2 = Qs[(ty*4+2)*SP + d], a3 = Qs[(ty*4+3)*SP + d];
            float b0 = Ks[(tx*4+0)*SP + d], b1 = Ks[(tx*4+1)*SP + d];
            float b2 = Ks[(tx*4+2)*SP + d], b3 = Ks[(tx*4+3)*SP + d];
            s[0][0]+=a0*b0; s[0][1]+=a0*b1; s[0][2]+=a0*b2; s[0][3]+=a0*b3;
            s[1][0]+=a1*b0; s[1][1]+=a1*b1; s[1][2]+=a1*b2; s[1][3]+=a1*b3;
            s[2][0]+=a2*b0; s[2][1]+=a2*b1; s[2][2]+=a2*b2; s[2][3]+=a2*b3;
            s[3][0]+=a3*b0; s[3][1]+=a3*b1; s[3][2]+=a3*b2; s[3][3]+=a3*b3;
        }
        #pragma unroll
        for (int i = 0; i < 4; i++)
            #pragma unroll
            for (int j = 0; j < 4; j++) s[i][j] *= scale;

        // row max partials
        #pragma unroll
        for (int i = 0; i < 4; i++) {
            float mx = fmaxf(fmaxf(s[i][0], s[i][1]), fmaxf(s[i][2], s[i][3]));
            red[(ty*4+i)*17 + tx] = mx;
        }
        __syncthreads();

        float p[4][4], lsum[4], alpha[4];
        #pragma unroll
        for (int i = 0; i < 4; i++) {
            int r = ty*4 + i;
            float rm = red[r*17 + 0];
            #pragma unroll
            for (int k = 1; k < 16; k++) rm = fmaxf(rm, red[r*17 + k]);
            float nm = fmaxf(m_i[i], rm);
            alpha[i] = __expf(m_i[i] - nm);
            m_i[i] = nm;
            float ls = 0.f;
            #pragma unroll
            for (int j = 0; j < 4; j++) { p[i][j] = __expf(s[i][j] - nm); ls += p[i][j]; }
            lsum[i] = ls;
            #pragma unroll
            for (int j = 0; j < 4; j++) o_acc[i][j] *= alpha[i];
        }
        __syncthreads();
        #pragma unroll
        for (int i = 0; i < 4; i++) {
            red[(ty*4+i)*17 + tx] = lsum[i];
            #pragma unroll
            for (int j = 0; j < 4; j++) Ps[(ty*4+i)*SP + tx*4 + j] = p[i][j];
        }
        __syncthreads();
        #pragma unroll
        for (int i = 0; i < 4; i++) {
            int r = ty*4 + i;
            float rs = 0.f;
            #pragma unroll
            for (int k = 0; k < 16; k++) rs += red[r*17 + k];
            l_i[i] = l_i[i]*alpha[i] + rs;
        }
        for (int c = 0; c < 64; c++) {
            float p0 = Ps[(ty*4+0)*SP + c], p1 = Ps[(ty*4+1)*SP + c];
            float p2 = Ps[(ty*4+2)*SP + c], p3 = Ps[(ty*4+3)*SP + c];
            float v0 = Vs[c*SP + tx*4+0], v1 = Vs[c*SP + tx*4+1];
            float v2 = Vs[c*SP + tx*4+2], v3 = Vs[c*SP + tx*4+3];
            o_acc[0][0]+=p0*v0; o_acc[0][1]+=p0*v1; o_acc[0][2]+=p0*v2; o_acc[0][3]+=p0*v3;
            o_acc[1][0]+=p1*v0; o_acc[1][1]+=p1*v1; o_acc[1][2]+=p1*v2; o_acc[1][3]+=p1*v3;
            o_acc[2][0]+=p2*v0; o_acc[2][1]+=p2*v1; o_acc[2][2]+=p2*v2; o_acc[2][3]+=p2*v3;
            o_acc[3][0]+=p3*v0; o_acc[3][1]+=p3*v1; o_acc[3][2]+=p3*v2; o_acc[3][3]+=p3*v3;
        }
    }

    #pragma unroll
    for (int i = 0; i < 4; i++) {
        float inv = 1.f / l_i[i];
        size_t row = (size_t)((s0 + ty*4 + i)*BATCH + b)*DMODEL + h*64 + tx*4;
        #pragma unroll
        for (int j = 0; j < 4; j++) O[row + j] = o_acc[i][j] * inv;
    }
}

// ---------------- residual add + layernorm (in place into X) ----------------
__global__ __launch_bounds__(256) void add_ln_k(float* __restrict__ X,
                                                const float* __restrict__ R,
                                                const float* __restrict__ w,
                                                const float* __restrict__ b)
{
    int t = blockIdx.x;
    size_t off = (size_t)t*DMODEL + threadIdx.x*4;
    float4 xv = *(const float4*)(X + off);
    float4 rv = *(const float4*)(R + off);
    float v0 = xv.x + rv.x, v1 = xv.y + rv.y, v2 = xv.z + rv.z, v3 = xv.w + rv.w;
    float s  = v0+v1+v2+v3;
    float sq = v0*v0+v1*v1+v2*v2+v3*v3;

    __shared__ float ssum[8], ssq[8];
    __shared__ float s_mean, s_rstd;
    int lane = threadIdx.x & 31, wp = threadIdx.x >> 5;
    #pragma unroll
    for (int o = 16; o; o >>= 1) {
        s  += __shfl_xor_sync(0xffffffff, s, o);
        sq += __shfl_xor_sync(0xffffffff, sq, o);
    }
    if (lane == 0) { ssum[wp] = s; ssq[wp] = sq; }
    __syncthreads();
    if (threadIdx.x == 0) {
        float S = 0.f, Q = 0.f;
        #pragma unroll
        for (int k = 0; k < 8; k++) { S += ssum[k]; Q += ssq[k]; }
        float mean = S * (1.f/DMODEL);
        float var  = Q * (1.f/DMODEL) - mean*mean;
        s_mean = mean;
        s_rstd = rsqrtf(var + LNEPS);
    }
    __syncthreads();
    float mean = s_mean, rs = s_rstd;
    int c = threadIdx.x*4;
    float4 out;
    out.x = (v0-mean)*rs*w[c+0] + b[c+0];
    out.y = (v1-mean)*rs*w[c+1] + b[c+1];
    out.z = (v2-mean)*rs*w[c+2] + b[c+2];
    out.w = (v3-mean)*rs*w[c+3] + b[c+3];
    *(float4*)(X + off) = out;
}

// ---------------- MoE gate: warp per token, top-2 softmax ----------------
__global__ __launch_bounds__(256) void gate_k(const float* __restrict__ X,
                                              const float* __restrict__ gw,
                                              const float* __restrict__ gb,
                                              int* __restrict__ topi, float* __restrict__ topp,
                                              int* __restrict__ counts, float* __restrict__ usage)
{
    int wp = threadIdx.x >> 5, lane = threadIdx.x & 31;
    int t = blockIdx.x * 8 + wp;
    const float* xr = X + (size_t)t*DMODEL;
    float acc[NEXP];
    #pragma unroll
    for (int e = 0; e < NEXP; e++) acc[e] = 0.f;
    for (int d = lane; d < DMODEL; d += 32) {
        float xv = xr[d];
        #pragma unroll
        for (int e = 0; e < NEXP; e++) acc[e] += xv * gw[e*DMODEL + d];
    }
    #pragma unroll
    for (int e = 0; e < NEXP; e++)
        #pragma unroll
        for (int o = 16; o; o >>= 1) acc[e] += __shfl_down_sync(0xffffffff, acc[e], o);
    if (lane == 0) {
        float sc[NEXP];
        #pragma unroll
        for (int e = 0; e < NEXP; e++) sc[e] = acc[e] + gb[e];
        int i1 = 0;
        #pragma unroll
        for (int e = 1; e < NEXP; e++) if (sc[e] > sc[i1]) i1 = e;
        int i2 = -1;
        #pragma unroll
        for (int e = 0; e < NEXP; e++) if (e != i1 && (i2 < 0 || sc[e] > sc[i2])) i2 = e;
        float e2 = __expf(sc[i2] - sc[i1]);
        float inv = 1.f / (1.f + e2);
        float p1 = inv, p2 = e2 * inv;
        topi[2*t] = i1; topi[2*t+1] = i2;
        topp[2*t] = p1; topp[2*t+1] = p2;
        atomicAdd(&counts[i1], 1); atomicAdd(&counts[i2], 1);
        atomicAdd(&usage[i1], p1); atomicAdd(&usage[i2], p2);
    }
}

__global__ void scan_k(const int* __restrict__ counts, int* __restrict__ segoff) {
    if (threadIdx.x == 0) {
        int run = 0;
        for (int e = 0; e < NEXP; e++) { segoff[e] = run; run += counts[e]; }
    }
}

__global__ void fill_k(const int* __restrict__ topi, const float* __restrict__ topp,
                       const int* __restrict__ segoff, int* __restrict__ cursor,
                       int* __restrict__ tokidx, float* __restrict__ tokprob)
{
    int t = blockIdx.x*256 + threadIdx.x;
    #pragma unroll
    for (int j = 0; j < 2; j++) {
        int e = topi[2*t + j];
        int slot = atomicAdd(&cursor[e], 1);
        int p = segoff[e] + slot;
        tokidx[p] = t;
        tokprob[p] = topp[2*t + j];
    }
}

// ---------------- finalize: copy X -> out, compute aux entropy ----------------
__global__ void finalize_k(const float* __restrict__ X, const float* __restrict__ usage,
                           float* __restrict__ out, size_t n, long auxpos)
{
    size_t i = (size_t)blockIdx.x*blockDim.x + threadIdx.x;
    size_t st = (size_t)gridDim.x*blockDim.x;
    for (; i < n; i += st) out[i] = X[i];
    if (blockIdx.x == 0 && threadIdx.x == 0 && auxpos >= 0) {
        float aux = 0.f;
        for (int l = 0; l < LAYERS; l++) {
            float sum = 0.f;
            for (int e = 0; e < NEXP; e++) sum += usage[l*NEXP + e];
            float ent = 0.f;
            for (int e = 0; e < NEXP; e++) {
                float p = usage[l*NEXP + e] / sum;
                ent -= p * logf(p + 1e-9f);
            }
            aux += ent * (1.f / LAYERS);
        }
        out[auxpos] = aux;
    }
}

// ---------------- host orchestration ----------------
extern "C" void kernel_launch(void* const* d_in, const int* in_sizes, int n_in,
                              void* d_out, int out_size)
{
    (void)in_sizes; (void)n_in;
    const float* src    = (const float*)d_in[0];
    const float* pos    = (const float*)d_in[1];
    const float* qkv_w  = (const float*)d_in[2];
    const float* qkv_b  = (const float*)d_in[3];
    const float* out_w  = (const float*)d_in[4];
    const float* out_b  = (const float*)d_in[5];
    const float* ln1_w  = (const float*)d_in[6];
    const float* ln1_b  = (const float*)d_in[7];
    const float* ln2_w  = (const float*)d_in[8];
    const float* ln2_b  = (const float*)d_in[9];
    const float* gate_w = (const float*)d_in[10];
    const float* gate_b = (const float*)d_in[11];
    const float* w1     = (const float*)d_in[12];
    const float* b1     = (const float*)d_in[13];
    const float* w2     = (const float*)d_in[14];
    const float* b2     = (const float*)d_in[15];
    float* out = (float*)d_out;

    float *pX, *pQKin, *pQK, *pV, *pO, *pAttn, *pMoe, *pH, *pTopp, *pTokprob, *pUsage;
    int *pTopi, *pCounts, *pSegoff, *pCursor, *pTokidx;
    cudaGetSymbolAddress((void**)&pX, g_X);
    cudaGetSymbolAddress((void**)&pQKin, g_QKin);
    cudaGetSymbolAddress((void**)&pQK, g_QK);
    cudaGetSymbolAddress((void**)&pV, g_V);
    cudaGetSymbolAddress((void**)&pO, g_O);
    cudaGetSymbolAddress((void**)&pAttn, g_Attn);
    cudaGetSymbolAddress((void**)&pMoe, g_Moe);
    cudaGetSymbolAddress((void**)&pH, g_H);
    cudaGetSymbolAddress((void**)&pTopi, g_topi);
    cudaGetSymbolAddress((void**)&pTopp, g_topp);
    cudaGetSymbolAddress((void**)&pCounts, g_counts);
    cudaGetSymbolAddress((void**)&pSegoff, g_segoff);
    cudaGetSymbolAddress((void**)&pCursor, g_cursor);
    cudaGetSymbolAddress((void**)&pTokidx, g_tokidx);
    cudaGetSymbolAddress((void**)&pTokprob, g_tokprob);
    cudaGetSymbolAddress((void**)&pUsage, g_usage);

    cudaFuncSetAttribute(flash_k, cudaFuncAttributeMaxDynamicSharedMemorySize, 72*1024);

    const size_t TD = (size_t)NTOK * DMODEL;

    copy_k<<<4096, 256>>>(src, pX, TD);
    zero_k<<<1, 64>>>(pUsage, LAYERS*NEXP, nullptr, nullptr, 0);

    for (int l = 0; l < LAYERS; l++) {
        const float* qkvw_l = qkv_w + (size_t)l*3*DMODEL*DMODEL;
        const float* qkvb_l = qkv_b + (size_t)l*3*DMODEL;
        const float* outw_l = out_w + (size_t)l*DMODEL*DMODEL;
        const float* outb_l = out_b + (size_t)l*DMODEL;
        const float* gw_l   = gate_w + (size_t)l*NEXP*DMODEL;
        const float* gb_l   = gate_b + (size_t)l*NEXP;
        const float* w1_l   = w1 + (size_t)l*NEXP*FFDIM*DMODEL;
        const float* b1_l   = b1 + (size_t)l*NEXP*FFDIM;
        const float* w2_l   = w2 + (size_t)l*NEXP*DMODEL*FFDIM;
        const float* b2_l   = b2 + (size_t)l*NEXP*DMODEL;

        // qk_in = X + pos
        add_k<<<4096, 256>>>(pX, pos, pQKin, TD);
        // Q|K fused GEMM: [T,1024] x [2048,1024]^T -> [T,2048]
        gemm_k<0><<<dim3(16, 64), 256>>>(pQKin, DMODEL, qkvw_l, DMODEL, qkvb_l,
                                         pQK, 2*DMODEL, NTOK, 2*DMODEL, DMODEL,
                                         nullptr, nullptr, nullptr, nullptr, 0, 0, nullptr);
        // V GEMM: X x wv^T
        gemm_k<0><<<dim3(8, 64), 256>>>(pX, DMODEL, qkvw_l + (size_t)2*DMODEL*DMODEL, DMODEL,
                                        qkvb_l + 2*DMODEL, pV, DMODEL, NTOK, DMODEL, DMODEL,
                                        nullptr, nullptr, nullptr, nullptr, 0, 0, nullptr);
        // flash attention
        flash_k<<<dim3(16, 128), 256, FLASH_SMEM>>>(pQK, pV, pO);
        // output projection
        gemm_k<0><<<dim3(8, 64), 256>>>(pO, DMODEL, outw_l, DMODEL, outb_l,
                                        pAttn, DMODEL, NTOK, DMODEL, DMODEL,
                                        nullptr, nullptr, nullptr, nullptr, 0, 0, nullptr);
        // X = LN(X + attn)
        add_ln_k<<<NTOK, 256>>>(pX, pAttn, ln1_w + (size_t)l*DMODEL, ln1_b + (size_t)l*DMODEL);

        // MoE
        zero_k<<<4096, 256>>>(pMoe, TD, pCounts, pCursor, NEXP);
        gate_k<<<NTOK/8, 256>>>(pX, gw_l, gb_l, pTopi, pTopp, pCounts, pUsage + l*NEXP);
        scan_k<<<1, 32>>>(pCounts, pSegoff);
        fill_k<<<NTOK/256, 256>>>(pTopi, pTopp, pSegoff, pCursor, pTokidx, pTokprob);
        // FF1 (gathered rows, ReLU): per expert [n_e,1024] x [4096,1024]^T
        gemm_k<1><<<dim3(FFDIM/128, NTOK/128, NEXP), 256>>>(
            pX, DMODEL, w1_l, DMODEL, b1_l, pH, FFDIM, NTOK, FFDIM, DMODEL,
            pTokidx, pTokprob, pSegoff, pCounts, (size_t)FFDIM*DMODEL, FFDIM, nullptr);
        // FF2 (scatter weighted): per expert [n_e,4096] x [1024,4096]^T -> atomic into moe_out
        gemm_k<2><<<dim3(DMODEL/128, NTOK/128, NEXP), 256>>>(
            pH, FFDIM, w2_l, FFDIM, b2_l, nullptr, DMODEL, NTOK, DMODEL, FFDIM,
            pTokidx, pTokprob, pSegoff, pCounts, (size_t)DMODEL*FFDIM, DMODEL, pMoe);
        // X = LN(X + moe)
        add_ln_k<<<NTOK, 256>>>(pX, pMoe, ln2_w + (size_t)l*DMODEL, ln2_b + (size_t)l*DMODEL);
    }

    long auxpos = ((size_t)out_size > TD) ? (long)TD : -1;
    size_t ncopy = ((size_t)out_size > TD) ? TD : (size_t)out_size;
    finalize_k<<<4096, 256>>>(pX, pUsage, out, ncopy, auxpos);
}

// round 5
// speedup vs baseline: 1.9677x; 1.9677x over previous
#include <cuda_runtime.h>
#include <cuda_bf16.h>
#include <math.h>
#include <stdint.h>

#define LAYERS 2
#define DMODEL 1024
#define NHEAD 16
#define HDIM 64
#define FFDIM 4096
#define NEXP 8
#define SEQ 1024
#define BATCH 8
#define NTOK (SEQ*BATCH)          // 8192
#define LNEPS 1e-5f

// ================= persistent scratch =================
__device__ __align__(16) float g_X[(size_t)NTOK*DMODEL];
__device__ __align__(16) float g_QK[(size_t)NTOK*2*DMODEL];
__device__ __align__(16) float g_V[(size_t)NTOK*DMODEL];
__device__ __align__(16) float g_O[(size_t)NTOK*DMODEL];
__device__ __align__(16) float g_Attn[(size_t)NTOK*DMODEL];
__device__ __align__(16) float g_Moe[(size_t)NTOK*DMODEL];
__device__ int   g_topi[NTOK*2];
__device__ float g_topp[NTOK*2];
__device__ int   g_counts[NEXP];
__device__ int   g_segoff[NEXP];
__device__ int   g_cursor[NEXP];
__device__ int   g_tokidx[2*NTOK];
__device__ float g_tokprob[2*NTOK];
__device__ float g_usage[LAYERS*NEXP];

// bf16 hi/lo splits
__device__ __align__(16) __nv_bfloat16 g_XH[(size_t)NTOK*DMODEL];
__device__ __align__(16) __nv_bfloat16 g_XL[(size_t)NTOK*DMODEL];
__device__ __align__(16) __nv_bfloat16 g_QKinH[(size_t)NTOK*DMODEL];
__device__ __align__(16) __nv_bfloat16 g_QKinL[(size_t)NTOK*DMODEL];
__device__ __align__(16) __nv_bfloat16 g_OH[(size_t)NTOK*DMODEL];
__device__ __align__(16) __nv_bfloat16 g_OL[(size_t)NTOK*DMODEL];
__device__ __align__(16) __nv_bfloat16 g_HH[(size_t)2*NTOK*FFDIM];
__device__ __align__(16) __nv_bfloat16 g_HL[(size_t)2*NTOK*FFDIM];
__device__ __align__(16) __nv_bfloat16 g_WqkvH[(size_t)LAYERS*3*DMODEL*DMODEL];
__device__ __align__(16) __nv_bfloat16 g_WqkvL[(size_t)LAYERS*3*DMODEL*DMODEL];
__device__ __align__(16) __nv_bfloat16 g_WoH[(size_t)LAYERS*DMODEL*DMODEL];
__device__ __align__(16) __nv_bfloat16 g_WoL[(size_t)LAYERS*DMODEL*DMODEL];
__device__ __align__(16) __nv_bfloat16 g_W1H[(size_t)LAYERS*NEXP*FFDIM*DMODEL];
__device__ __align__(16) __nv_bfloat16 g_W1L[(size_t)LAYERS*NEXP*FFDIM*DMODEL];
__device__ __align__(16) __nv_bfloat16 g_W2H[(size_t)LAYERS*NEXP*DMODEL*FFDIM];
__device__ __align__(16) __nv_bfloat16 g_W2L[(size_t)LAYERS*NEXP*DMODEL*FFDIM];

// ================= helpers =================
__device__ __forceinline__ uint32_t s2u(const void* p) {
    uint32_t a;
    asm("{ .reg .u64 t; cvta.to.shared.u64 t, %1; cvt.u32.u64 %0, t; }" : "=r"(a) : "l"(p));
    return a;
}
#define CP_ASYNC(dst, src, sz) \
    asm volatile("cp.async.ca.shared.global [%0], [%1], 16, %2;" :: "r"(dst), "l"(src), "r"(sz))
#define CP_COMMIT() asm volatile("cp.async.commit_group;" ::: "memory")
#define CP_WAIT0()  asm volatile("cp.async.wait_group 0;" ::: "memory")
#define CP_WAIT1()  asm volatile("cp.async.wait_group 1;" ::: "memory")

__device__ __forceinline__ void mma16816(float* c, const uint32_t* a, const uint32_t* b) {
    asm volatile(
        "mma.sync.aligned.m16n8k16.row.col.f32.bf16.bf16.f32 "
        "{%0,%1,%2,%3}, {%4,%5,%6,%7}, {%8,%9}, {%0,%1,%2,%3};"
        : "+f"(c[0]), "+f"(c[1]), "+f"(c[2]), "+f"(c[3])
        : "r"(a[0]), "r"(a[1]), "r"(a[2]), "r"(a[3]), "r"(b[0]), "r"(b[1]));
}

// smem: 2 stages x [Ah|Al|Bh|Bl], each tile 128 rows x 40 bf16 (padded from 32)
#define LDK 40
#define TILE_B (128*LDK*2)          // 10240
#define OFF_AH 0
#define OFF_AL (1*TILE_B)
#define OFF_BH (2*TILE_B)
#define OFF_BL (3*TILE_B)
#define STG_B  (4*TILE_B)           // 40960
#define SM_AROW (2*STG_B)           // 81920
#define SM_TOT  (SM_AROW + 512)     // 82432

// ================= emulated-fp32 HMMA GEMM =================
// C[128,128 tile] = A[M,K]*B[N,K]^T + bias  via Ah*Bh + Ah*Bl + Al*Bh (bf16 split-3)
// MODE 0: dense fp32 out.
// MODE 1: expert FF1: gather A rows via tokidx, ReLU, split-bf16 out (contiguous seg rows).
// MODE 2: expert FF2: contiguous A rows, prob-weighted atomicAdd scatter to fp32.
template<int MODE>
__global__ __launch_bounds__(256, 1) void tgemm_k(
    const __nv_bfloat16* __restrict__ Ah, const __nv_bfloat16* __restrict__ Al, int lda,
    const __nv_bfloat16* __restrict__ Bh_, const __nv_bfloat16* __restrict__ Bl_, int ldb,
    const float* __restrict__ bias,
    float* __restrict__ C, int ldc,
    int M, int Kd,
    const int* __restrict__ tokidx, const float* __restrict__ tokprob,
    const int* __restrict__ segoff, const int* __restrict__ counts,
    size_t w_stride, int b_stride,
    __nv_bfloat16* __restrict__ HhOut, __nv_bfloat16* __restrict__ HlOut,
    float* __restrict__ scat)
{
    int base = 0;
    const __nv_bfloat16* Bh = Bh_;
    const __nv_bfloat16* Bl = Bl_;
    if (MODE != 0) {
        int e = blockIdx.z;
        base = segoff[e];
        M = counts[e];
        Bh += (size_t)e * w_stride;
        Bl += (size_t)e * w_stride;
        bias += (size_t)e * b_stride;
    }
    int m0 = blockIdx.y * 128;
    if (m0 >= M) return;
    int n0 = blockIdx.x * 128;

    extern __shared__ char smem[];
    uint32_t sbase = s2u(smem);
    int* arow = (int*)(smem + SM_AROW);

    int tid = threadIdx.x;
    int wid = tid >> 5, lid = tid & 31;
    int g8 = lid >> 2, t4 = lid & 3;
    int warpM = wid >> 2, warpN = wid & 3;

    if (tid < 128) {
        int r = m0 + tid;
        int g = -1;
        if (r < M) {
            if (MODE == 1)      g = tokidx[base + r];
            else if (MODE == 2) g = base + r;
            else                g = r;
        }
        arow[tid] = g;
    }
    __syncthreads();

    const int NC = Kd >> 5;   // K chunks of 32

    auto load_stage = [&](int c, int s) {
        int k0 = c << 5;
        uint32_t tb = sbase + s * STG_B;
        #pragma unroll
        for (int i = 0; i < 2; i++) {
            int v  = tid + i * 256;     // 0..511
            int r  = v >> 2;            // 0..127
            int ce = (v & 3) * 8;       // element col (8 bf16 = 16B)
            uint32_t soff = (uint32_t)((r * LDK + ce) * 2);
            int g = arow[r];
            int grow = g >= 0 ? g : 0;
            int sz = g >= 0 ? 16 : 0;
            const char* pah = (const char*)(Ah + (size_t)grow * lda + k0 + ce);
            const char* pal = (const char*)(Al + (size_t)grow * lda + k0 + ce);
            CP_ASYNC(tb + OFF_AH + soff, pah, sz);
            CP_ASYNC(tb + OFF_AL + soff, pal, sz);
            const char* pbh = (const char*)(Bh + (size_t)(n0 + r) * ldb + k0 + ce);
            const char* pbl = (const char*)(Bl + (size_t)(n0 + r) * ldb + k0 + ce);
            CP_ASYNC(tb + OFF_BH + soff, pbh, 16);
            CP_ASYNC(tb + OFF_BL + soff, pbl, 16);
        }
        CP_COMMIT();
    };

    float acc[4][4][4];
    #pragma unroll
    for (int mt = 0; mt < 4; mt++)
        #pragma unroll
        for (int nt = 0; nt < 4; nt++)
            #pragma unroll
            for (int q = 0; q < 4; q++) acc[mt][nt][q] = 0.f;

    load_stage(0, 0);

    for (int c = 0; c < NC; c++) {
        int s = c & 1;
        if (c + 1 < NC) { load_stage(c + 1, s ^ 1); CP_WAIT1(); }
        else           { CP_WAIT0(); }
        __syncthreads();

        const char* tb = smem + s * STG_B;
        #pragma unroll
        for (int ks = 0; ks < 2; ks++) {
            int kb = ks * 16 + t4 * 2;
            uint32_t ah[4][4], al[4][4];
            #pragma unroll
            for (int mt = 0; mt < 4; mt++) {
                int r0 = warpM * 64 + mt * 16 + g8;
                ah[mt][0] = *(const uint32_t*)(tb + OFF_AH + (r0*LDK + kb)*2);
                ah[mt][1] = *(const uint32_t*)(tb + OFF_AH + ((r0+8)*LDK + kb)*2);
                ah[mt][2] = *(const uint32_t*)(tb + OFF_AH + (r0*LDK + kb+8)*2);
                ah[mt][3] = *(const uint32_t*)(tb + OFF_AH + ((r0+8)*LDK + kb+8)*2);
                al[mt][0] = *(const uint32_t*)(tb + OFF_AL + (r0*LDK + kb)*2);
                al[mt][1] = *(const uint32_t*)(tb + OFF_AL + ((r0+8)*LDK + kb)*2);
                al[mt][2] = *(const uint32_t*)(tb + OFF_AL + (r0*LDK + kb+8)*2);
                al[mt][3] = *(const uint32_t*)(tb + OFF_AL + ((r0+8)*LDK + kb+8)*2);
            }
            uint32_t bh[4][2], bl[4][2];
            #pragma unroll
            for (int nt = 0; nt < 4; nt++) {
                int rn = warpN * 32 + nt * 8 + g8;
                bh[nt][0] = *(const uint32_t*)(tb + OFF_BH + (rn*LDK + kb)*2);
                bh[nt][1] = *(const uint32_t*)(tb + OFF_BH + (rn*LDK + kb+8)*2);
                bl[nt][0] = *(const uint32_t*)(tb + OFF_BL + (rn*LDK + kb)*2);
                bl[nt][1] = *(const uint32_t*)(tb + OFF_BL + (rn*LDK + kb+8)*2);
            }
            #pragma unroll
            for (int mt = 0; mt < 4; mt++)
                #pragma unroll
                for (int nt = 0; nt < 4; nt++) {
                    mma16816(acc[mt][nt], ah[mt], bh[nt]);
                    mma16816(acc[mt][nt], ah[mt], bl[nt]);
                    mma16816(acc[mt][nt], al[mt], bh[nt]);
                }
        }
        __syncthreads();
    }

    // ---------------- epilogue ----------------
    #pragma unroll
    for (int mt = 0; mt < 4; mt++) {
        int r0 = warpM * 64 + mt * 16 + g8;
        #pragma unroll
        for (int half = 0; half < 2; half++) {
            int r = r0 + half * 8;
            if (arow[r] < 0) continue;
            #pragma unroll
            for (int nt = 0; nt < 4; nt++) {
                int gcol = n0 + warpN * 32 + nt * 8 + t4 * 2;
                float v0 = acc[mt][nt][half*2 + 0] + bias[gcol];
                float v1 = acc[mt][nt][half*2 + 1] + bias[gcol + 1];
                if (MODE == 0) {
                    float2 v; v.x = v0; v.y = v1;
                    *(float2*)(C + (size_t)(m0 + r) * ldc + gcol) = v;
                } else if (MODE == 1) {
                    v0 = v0 > 0.f ? v0 : 0.f;
                    v1 = v1 > 0.f ? v1 : 0.f;
                    __nv_bfloat16 h0 = __float2bfloat16(v0);
                    __nv_bfloat16 h1 = __float2bfloat16(v1);
                    __nv_bfloat16 l0 = __float2bfloat16(v0 - __bfloat162float(h0));
                    __nv_bfloat16 l1 = __float2bfloat16(v1 - __bfloat162float(h1));
                    size_t hrow = (size_t)(base + m0 + r) * ldc + gcol;
                    __nv_bfloat162 ph; ph.x = h0; ph.y = h1;
                    __nv_bfloat162 pl; pl.x = l0; pl.y = l1;
                    *(__nv_bfloat162*)(HhOut + hrow) = ph;
                    *(__nv_bfloat162*)(HlOut + hrow) = pl;
                } else {
                    int   tok = tokidx[base + m0 + r];
                    float p   = tokprob[base + m0 + r];
                    float* orow = scat + (size_t)tok * DMODEL + gcol;
                    atomicAdd(orow,     p * v0);
                    atomicAdd(orow + 1, p * v1);
                }
            }
        }
    }
}

// ================= splits / elementwise =================
__global__ void split_k(const float* __restrict__ in,
                        __nv_bfloat16* __restrict__ oh, __nv_bfloat16* __restrict__ ol, size_t n) {
    size_t i = (size_t)blockIdx.x*blockDim.x + threadIdx.x;
    size_t st = (size_t)gridDim.x*blockDim.x;
    for (; i < n; i += st) {
        float v = in[i];
        __nv_bfloat16 h = __float2bfloat16(v);
        oh[i] = h;
        ol[i] = __float2bfloat16(v - __bfloat162float(h));
    }
}
__global__ void addsplit_k(const float* __restrict__ a, const float* __restrict__ b,
                           __nv_bfloat16* __restrict__ oh, __nv_bfloat16* __restrict__ ol, size_t n) {
    size_t i = (size_t)blockIdx.x*blockDim.x + threadIdx.x;
    size_t st = (size_t)gridDim.x*blockDim.x;
    for (; i < n; i += st) {
        float v = a[i] + b[i];
        __nv_bfloat16 h = __float2bfloat16(v);
        oh[i] = h;
        ol[i] = __float2bfloat16(v - __bfloat162float(h));
    }
}
__global__ void copy_k(const float* __restrict__ a, float* __restrict__ o, size_t n) {
    size_t i = (size_t)blockIdx.x*blockDim.x + threadIdx.x;
    size_t st = (size_t)gridDim.x*blockDim.x;
    for (; i < n; i += st) o[i] = a[i];
}
__global__ void zero_k(float* __restrict__ p, size_t n, int* a, int* b, int nc) {
    size_t i = (size_t)blockIdx.x*blockDim.x + threadIdx.x;
    size_t st = (size_t)gridDim.x*blockDim.x;
    for (; i < n; i += st) p[i] = 0.f;
    if (blockIdx.x == 0 && (int)threadIdx.x < nc) {
        if (a) a[threadIdx.x] = 0;
        if (b) b[threadIdx.x] = 0;
    }
}

// ================= flash attention =================
#define SP 65
#define FLASH_SMEM ((4*64*SP + 64*17) * 4)

__global__ __launch_bounds__(256) void flash_k(const float* __restrict__ QK,
                                               const float* __restrict__ V,
                                               float* __restrict__ O)
{
    extern __shared__ float sm[];
    float* Qs  = sm;
    float* Ks  = Qs + 64*SP;
    float* Vs  = Ks + 64*SP;
    float* Ps  = Vs + 64*SP;
    float* red = Ps + 64*SP;

    int tid = threadIdx.x;
    int tx = tid & 15, ty = tid >> 4;
    int bh = blockIdx.y;
    int b  = bh >> 4;
    int h  = bh & 15;
    int s0 = blockIdx.x * 64;

    #pragma unroll
    for (int i = 0; i < 4; i++) {
        int r = ty + i*16;
        int d = tx * 4;
        float4 q = *(const float4*)(QK + ((size_t)((s0+r)*BATCH + b))*2048 + h*64 + d);
        Qs[r*SP + d]   = q.x; Qs[r*SP + d+1] = q.y;
        Qs[r*SP + d+2] = q.z; Qs[r*SP + d+3] = q.w;
    }

    float m_i[4], l_i[4], o_acc[4][4];
    #pragma unroll
    for (int i = 0; i < 4; i++) {
        m_i[i] = -1e30f; l_i[i] = 0.f;
        #pragma unroll
        for (int j = 0; j < 4; j++) o_acc[i][j] = 0.f;
    }
    const float scale = 0.125f;

    for (int t0 = 0; t0 < SEQ; t0 += 64) {
        __syncthreads();
        #pragma unroll
        for (int i = 0; i < 4; i++) {
            int r = ty + i*16;
            int d = tx * 4;
            size_t tok = (size_t)((t0+r)*BATCH + b);
            float4 kv = *(const float4*)(QK + tok*2048 + DMODEL + h*64 + d);
            Ks[r*SP + d]   = kv.x; Ks[r*SP + d+1] = kv.y;
            Ks[r*SP + d+2] = kv.z; Ks[r*SP + d+3] = kv.w;
            float4 vv = *(const float4*)(V + tok*DMODEL + h*64 + d);
            Vs[r*SP + d]   = vv.x; Vs[r*SP + d+1] = vv.y;
            Vs[r*SP + d+2] = vv.z; Vs[r*SP + d+3] = vv.w;
        }
        __syncthreads();

        float s[4][4];
        #pragma unroll
        for (int i = 0; i < 4; i++)
            #pragma unroll
            for (int j = 0; j < 4; j++) s[i][j] = 0.f;
        for (int d = 0; d < 64; d++) {
            float a0 = Qs[(ty*4+0)*SP + d], a1 = Qs[(ty*4+1)*SP + d];
            float a2 = Qs[(ty*4+2)*SP + d], a3 = Qs[(ty*4+3)*SP + d];
            float b0 = Ks[(tx*4+0)*SP + d], b1 = Ks[(tx*4+1)*SP + d];
            float b2 = Ks[(tx*4+2)*SP + d], b3 = Ks[(tx*4+3)*SP + d];
            s[0][0]+=a0*b0; s[0][1]+=a0*b1; s[0][2]+=a0*b2; s[0][3]+=a0*b3;
            s[1][0]+=a1*b0; s[1][1]+=a1*b1; s[1][2]+=a1*b2; s[1][3]+=a1*b3;
            s[2][0]+=a2*b0; s[2][1]+=a2*b1; s[2][2]+=a2*b2; s[2][3]+=a2*b3;
            s[3][0]+=a3*b0; s[3][1]+=a3*b1; s[3][2]+=a3*b2; s[3][3]+=a3*b3;
        }
        #pragma unroll
        for (int i = 0; i < 4; i++)
            #pragma unroll
            for (int j = 0; j < 4; j++) s[i][j] *= scale;

        #pragma unroll
        for (int i = 0; i < 4; i++) {
            float mx = fmaxf(fmaxf(s[i][0], s[i][1]), fmaxf(s[i][2], s[i][3]));
            red[(ty*4+i)*17 + tx] = mx;
        }
        __syncthreads();

        float p[4][4], lsum[4], alpha[4];
        #pragma unroll
        for (int i = 0; i < 4; i++) {
            int r = ty*4 + i;
            float rm = red[r*17 + 0];
            #pragma unroll
            for (int k = 1; k < 16; k++) rm = fmaxf(rm, red[r*17 + k]);
            float nm = fmaxf(m_i[i], rm);
            alpha[i] = __expf(m_i[i] - nm);
            m_i[i] = nm;
            float ls = 0.f;
            #pragma unroll
            for (int j = 0; j < 4; j++) { p[i][j] = __expf(s[i][j] - nm); ls += p[i][j]; }
            lsum[i] = ls;
            #pragma unroll
            for (int j = 0; j < 4; j++) o_acc[i][j] *= alpha[i];
        }
        __syncthreads();
        #pragma unroll
        for (int i = 0; i < 4; i++) {
            red[(ty*4+i)*17 + tx] = lsum[i];
            #pragma unroll
            for (int j = 0; j < 4; j++) Ps[(ty*4+i)*SP + tx*4 + j] = p[i][j];
        }
        __syncthreads();
        #pragma unroll
        for (int i = 0; i < 4; i++) {
            int r = ty*4 + i;
            float rs = 0.f;
            #pragma unroll
            for (int k = 0; k < 16; k++) rs += red[r*17 + k];
            l_i[i] = l_i[i]*alpha[i] + rs;
        }
        for (int c = 0; c < 64; c++) {
            float p0 = Ps[(ty*4+0)*SP + c], p1 = Ps[(ty*4+1)*SP + c];
            float p2 = Ps[(ty*4+2)*SP + c], p3 = Ps[(ty*4+3)*SP + c];
            float v0 = Vs[c*SP + tx*4+0], v1 = Vs[c*SP + tx*4+1];
            float v2 = Vs[c*SP + tx*4+2], v3 = Vs[c*SP + tx*4+3];
            o_acc[0][0]+=p0*v0; o_acc[0][1]+=p0*v1; o_acc[0][2]+=p0*v2; o_acc[0][3]+=p0*v3;
            o_acc[1][0]+=p1*v0; o_acc[1][1]+=p1*v1; o_acc[1][2]+=p1*v2; o_acc[1][3]+=p1*v3;
            o_acc[2][0]+=p2*v0; o_acc[2][1]+=p2*v1; o_acc[2][2]+=p2*v2; o_acc[2][3]+=p2*v3;
            o_acc[3][0]+=p3*v0; o_acc[3][1]+=p3*v1; o_acc[3][2]+=p3*v2; o_acc[3][3]+=p3*v3;
        }
    }

    #pragma unroll
    for (int i = 0; i < 4; i++) {
        float inv = 1.f / l_i[i];
        size_t row = (size_t)((s0 + ty*4 + i)*BATCH + b)*DMODEL + h*64 + tx*4;
        #pragma unroll
        for (int j = 0; j < 4; j++) O[row + j] = o_acc[i][j] * inv;
    }
}

// ================= residual + layernorm =================
__global__ __launch_bounds__(256) void add_ln_k(float* __restrict__ X,
                                                const float* __restrict__ R,
                                                const float* __restrict__ w,
                                                const float* __restrict__ b)
{
    int t = blockIdx.x;
    size_t off = (size_t)t*DMODEL + threadIdx.x*4;
    float4 xv = *(const float4*)(X + off);
    float4 rv = *(const float4*)(R + off);
    float v0 = xv.x + rv.x, v1 = xv.y + rv.y, v2 = xv.z + rv.z, v3 = xv.w + rv.w;
    float s  = v0+v1+v2+v3;
    float sq = v0*v0+v1*v1+v2*v2+v3*v3;

    __shared__ float ssum[8], ssq[8];
    __shared__ float s_mean, s_rstd;
    int lane = threadIdx.x & 31, wp = threadIdx.x >> 5;
    #pragma unroll
    for (int o = 16; o; o >>= 1) {
        s  += __shfl_xor_sync(0xffffffff, s, o);
        sq += __shfl_xor_sync(0xffffffff, sq, o);
    }
    if (lane == 0) { ssum[wp] = s; ssq[wp] = sq; }
    __syncthreads();
    if (threadIdx.x == 0) {
        float S = 0.f, Q = 0.f;
        #pragma unroll
        for (int k = 0; k < 8; k++) { S += ssum[k]; Q += ssq[k]; }
        float mean = S * (1.f/DMODEL);
        float var  = Q * (1.f/DMODEL) - mean*mean;
        s_mean = mean;
        s_rstd = rsqrtf(var + LNEPS);
    }
    __syncthreads();
    float mean = s_mean, rs = s_rstd;
    int c = threadIdx.x*4;
    float4 out;
    out.x = (v0-mean)*rs*w[c+0] + b[c+0];
    out.y = (v1-mean)*rs*w[c+1] + b[c+1];
    out.z = (v2-mean)*rs*w[c+2] + b[c+2];
    out.w = (v3-mean)*rs*w[c+3] + b[c+3];
    *(float4*)(X + off) = out;
}

// ================= MoE gate =================
__global__ __launch_bounds__(256) void gate_k(const float* __restrict__ X,
                                              const float* __restrict__ gw,
                                              const float* __restrict__ gb,
                                              int* __restrict__ topi, float* __restrict__ topp,
                                              int* __restrict__ counts, float* __restrict__ usage)
{
    int wp = threadIdx.x >> 5, lane = threadIdx.x & 31;
    int t = blockIdx.x * 8 + wp;
    const float* xr = X + (size_t)t*DMODEL;
    float acc[NEXP];
    #pragma unroll
    for (int e = 0; e < NEXP; e++) acc[e] = 0.f;
    for (int d = lane; d < DMODEL; d += 32) {
        float xv = xr[d];
        #pragma unroll
        for (int e = 0; e < NEXP; e++) acc[e] += xv * gw[e*DMODEL + d];
    }
    #pragma unroll
    for (int e = 0; e < NEXP; e++)
        #pragma unroll
        for (int o = 16; o; o >>= 1) acc[e] += __shfl_down_sync(0xffffffff, acc[e], o);
    if (lane == 0) {
        float sc[NEXP];
        #pragma unroll
        for (int e = 0; e < NEXP; e++) sc[e] = acc[e] + gb[e];
        int i1 = 0;
        #pragma unroll
        for (int e = 1; e < NEXP; e++) if (sc[e] > sc[i1]) i1 = e;
        int i2 = -1;
        #pragma unroll
        for (int e = 0; e < NEXP; e++) if (e != i1 && (i2 < 0 || sc[e] > sc[i2])) i2 = e;
        float e2 = __expf(sc[i2] - sc[i1]);
        float inv = 1.f / (1.f + e2);
        float p1 = inv, p2 = e2 * inv;
        topi[2*t] = i1; topi[2*t+1] = i2;
        topp[2*t] = p1; topp[2*t+1] = p2;
        atomicAdd(&counts[i1], 1); atomicAdd(&counts[i2], 1);
        atomicAdd(&usage[i1], p1); atomicAdd(&usage[i2], p2);
    }
}

__global__ void scan_k(const int* __restrict__ counts, int* __restrict__ segoff) {
    if (threadIdx.x == 0) {
        int run = 0;
        for (int e = 0; e < NEXP; e++) { segoff[e] = run; run += counts[e]; }
    }
}

__global__ void fill_k(const int* __restrict__ topi, const float* __restrict__ topp,
                       const int* __restrict__ segoff, int* __restrict__ cursor,
                       int* __restrict__ tokidx, float* __restrict__ tokprob)
{
    int t = blockIdx.x*256 + threadIdx.x;
    #pragma unroll
    for (int j = 0; j < 2; j++) {
        int e = topi[2*t + j];
        int slot = atomicAdd(&cursor[e], 1);
        int p = segoff[e] + slot;
        tokidx[p] = t;
        tokprob[p] = topp[2*t + j];
    }
}

// ================= finalize =================
__global__ void finalize_k(const float* __restrict__ X, const float* __restrict__ usage,
                           float* __restrict__ out, size_t n, long auxpos)
{
    size_t i = (size_t)blockIdx.x*blockDim.x + threadIdx.x;
    size_t st = (size_t)gridDim.x*blockDim.x;
    for (; i < n; i += st) out[i] = X[i];
    if (blockIdx.x == 0 && threadIdx.x == 0 && auxpos >= 0) {
        float aux = 0.f;
        for (int l = 0; l < LAYERS; l++) {
            float sum = 0.f;
            for (int e = 0; e < NEXP; e++) sum += usage[l*NEXP + e];
            float ent = 0.f;
            for (int e = 0; e < NEXP; e++) {
                float p = usage[l*NEXP + e] / sum;
                ent -= p * logf(p + 1e-9f);
            }
            aux += ent * (1.f / LAYERS);
        }
        out[auxpos] = aux;
    }
}

// ================= host orchestration =================
extern "C" void kernel_launch(void* const* d_in, const int* in_sizes, int n_in,
                              void* d_out, int out_size)
{
    (void)in_sizes; (void)n_in;
    const float* src    = (const float*)d_in[0];
    const float* pos    = (const float*)d_in[1];
    const float* qkv_w  = (const float*)d_in[2];
    const float* qkv_b  = (const float*)d_in[3];
    const float* out_w  = (const float*)d_in[4];
    const float* out_b  = (const float*)d_in[5];
    const float* ln1_w  = (const float*)d_in[6];
    const float* ln1_b  = (const float*)d_in[7];
    const float* ln2_w  = (const float*)d_in[8];
    const float* ln2_b  = (const float*)d_in[9];
    const float* gate_w = (const float*)d_in[10];
    const float* gate_b = (const float*)d_in[11];
    const float* w1     = (const float*)d_in[12];
    const float* b1     = (const float*)d_in[13];
    const float* w2     = (const float*)d_in[14];
    const float* b2     = (const float*)d_in[15];
    float* out = (float*)d_out;

    float *pX, *pQK, *pV, *pO, *pAttn, *pMoe, *pTopp, *pTokprob, *pUsage;
    int *pTopi, *pCounts, *pSegoff, *pCursor, *pTokidx;
    __nv_bfloat16 *pXH, *pXL, *pQKinH, *pQKinL, *pOH, *pOL, *pHH, *pHL;
    __nv_bfloat16 *pWqkvH, *pWqkvL, *pWoH, *pWoL, *pW1H, *pW1L, *pW2H, *pW2L;

    cudaGetSymbolAddress((void**)&pX, g_X);
    cudaGetSymbolAddress((void**)&pQK, g_QK);
    cudaGetSymbolAddress((void**)&pV, g_V);
    cudaGetSymbolAddress((void**)&pO, g_O);
    cudaGetSymbolAddress((void**)&pAttn, g_Attn);
    cudaGetSymbolAddress((void**)&pMoe, g_Moe);
    cudaGetSymbolAddress((void**)&pTopi, g_topi);
    cudaGetSymbolAddress((void**)&pTopp, g_topp);
    cudaGetSymbolAddress((void**)&pCounts, g_counts);
    cudaGetSymbolAddress((void**)&pSegoff, g_segoff);
    cudaGetSymbolAddress((void**)&pCursor, g_cursor);
    cudaGetSymbolAddress((void**)&pTokidx, g_tokidx);
    cudaGetSymbolAddress((void**)&pTokprob, g_tokprob);
    cudaGetSymbolAddress((void**)&pUsage, g_usage);
    cudaGetSymbolAddress((void**)&pXH, g_XH);
    cudaGetSymbolAddress((void**)&pXL, g_XL);
    cudaGetSymbolAddress((void**)&pQKinH, g_QKinH);
    cudaGetSymbolAddress((void**)&pQKinL, g_QKinL);
    cudaGetSymbolAddress((void**)&pOH, g_OH);
    cudaGetSymbolAddress((void**)&pOL, g_OL);
    cudaGetSymbolAddress((void**)&pHH, g_HH);
    cudaGetSymbolAddress((void**)&pHL, g_HL);
    cudaGetSymbolAddress((void**)&pWqkvH, g_WqkvH);
    cudaGetSymbolAddress((void**)&pWqkvL, g_WqkvL);
    cudaGetSymbolAddress((void**)&pWoH, g_WoH);
    cudaGetSymbolAddress((void**)&pWoL, g_WoL);
    cudaGetSymbolAddress((void**)&pW1H, g_W1H);
    cudaGetSymbolAddress((void**)&pW1L, g_W1L);
    cudaGetSymbolAddress((void**)&pW2H, g_W2H);
    cudaGetSymbolAddress((void**)&pW2L, g_W2L);

    cudaFuncSetAttribute(flash_k, cudaFuncAttributeMaxDynamicSharedMemorySize, 72*1024);
    cudaFuncSetAttribute(tgemm_k<0>, cudaFuncAttributeMaxDynamicSharedMemorySize, SM_TOT);
    cudaFuncSetAttribute(tgemm_k<1>, cudaFuncAttributeMaxDynamicSharedMemorySize, SM_TOT);
    cudaFuncSetAttribute(tgemm_k<2>, cudaFuncAttributeMaxDynamicSharedMemorySize, SM_TOT);

    const size_t TD = (size_t)NTOK * DMODEL;

    // split all weights to bf16 hi/lo (deterministic, every launch)
    split_k<<<4096, 256>>>(qkv_w, pWqkvH, pWqkvL, (size_t)LAYERS*3*DMODEL*DMODEL);
    split_k<<<4096, 256>>>(out_w, pWoH,  pWoL,  (size_t)LAYERS*DMODEL*DMODEL);
    split_k<<<8192, 256>>>(w1,    pW1H,  pW1L,  (size_t)LAYERS*NEXP*FFDIM*DMODEL);
    split_k<<<8192, 256>>>(w2,    pW2H,  pW2L,  (size_t)LAYERS*NEXP*DMODEL*FFDIM);

    copy_k<<<4096, 256>>>(src, pX, TD);
    zero_k<<<1, 64>>>(pUsage, LAYERS*NEXP, nullptr, nullptr, 0);

    for (int l = 0; l < LAYERS; l++) {
        const float* qkvb_l = qkv_b + (size_t)l*3*DMODEL;
        const float* outb_l = out_b + (size_t)l*DMODEL;
        const float* gw_l   = gate_w + (size_t)l*NEXP*DMODEL;
        const float* gb_l   = gate_b + (size_t)l*NEXP;
        const float* b1_l   = b1 + (size_t)l*NEXP*FFDIM;
        const float* b2_l   = b2 + (size_t)l*NEXP*DMODEL;
        const __nv_bfloat16* WqH = pWqkvH + (size_t)l*3*DMODEL*DMODEL;
        const __nv_bfloat16* WqL = pWqkvL + (size_t)l*3*DMODEL*DMODEL;
        const __nv_bfloat16* WoHl = pWoH + (size_t)l*DMODEL*DMODEL;
        const __nv_bfloat16* WoLl = pWoL + (size_t)l*DMODEL*DMODEL;
        const __nv_bfloat16* W1Hl = pW1H + (size_t)l*NEXP*FFDIM*DMODEL;
        const __nv_bfloat16* W1Ll = pW1L + (size_t)l*NEXP*FFDIM*DMODEL;
        const __nv_bfloat16* W2Hl = pW2H + (size_t)l*NEXP*DMODEL*FFDIM;
        const __nv_bfloat16* W2Ll = pW2L + (size_t)l*NEXP*DMODEL*FFDIM;

        // activation splits
        split_k<<<4096, 256>>>(pX, pXH, pXL, TD);                 // X (V gemm A)
        addsplit_k<<<4096, 256>>>(pX, pos, pQKinH, pQKinL, TD);   // X+pos (QK gemm A)

        // Q|K fused GEMM -> g_QK [T,2048]
        tgemm_k<0><<<dim3(16, 64), 256, SM_TOT>>>(
            pQKinH, pQKinL, DMODEL, WqH, WqL, DMODEL, qkvb_l,
            pQK, 2*DMODEL, NTOK, DMODEL,
            nullptr, nullptr, nullptr, nullptr, 0, 0, nullptr, nullptr, nullptr);
        // V GEMM -> g_V
        tgemm_k<0><<<dim3(8, 64), 256, SM_TOT>>>(
            pXH, pXL, DMODEL, WqH + (size_t)2*DMODEL*DMODEL, WqL + (size_t)2*DMODEL*DMODEL, DMODEL,
            qkvb_l + 2*DMODEL, pV, DMODEL, NTOK, DMODEL,
            nullptr, nullptr, nullptr, nullptr, 0, 0, nullptr, nullptr, nullptr);

        flash_k<<<dim3(16, 128), 256, FLASH_SMEM>>>(pQK, pV, pO);

        split_k<<<4096, 256>>>(pO, pOH, pOL, TD);
        // output projection -> g_Attn
        tgemm_k<0><<<dim3(8, 64), 256, SM_TOT>>>(
            pOH, pOL, DMODEL, WoHl, WoLl, DMODEL, outb_l,
            pAttn, DMODEL, NTOK, DMODEL,
            nullptr, nullptr, nullptr, nullptr, 0, 0, nullptr, nullptr, nullptr);

        add_ln_k<<<NTOK, 256>>>(pX, pAttn, ln1_w + (size_t)l*DMODEL, ln1_b + (size_t)l*DMODEL);
        split_k<<<4096, 256>>>(pX, pXH, pXL, TD);   // post-LN1 X (FF1 A)

        // MoE routing
        zero_k<<<4096, 256>>>(pMoe, TD, pCounts, pCursor, NEXP);
        gate_k<<<NTOK/8, 256>>>(pX, gw_l, gb_l, pTopi, pTopp, pCounts, pUsage + l*NEXP);
        scan_k<<<1, 32>>>(pCounts, pSegoff);
        fill_k<<<NTOK/256, 256>>>(pTopi, pTopp, pSegoff, pCursor, pTokidx, pTokprob);

        // FF1: gather rows of X, ReLU, write split-bf16 H
        tgemm_k<1><<<dim3(FFDIM/128, NTOK/128, NEXP), 256, SM_TOT>>>(
            pXH, pXL, DMODEL, W1Hl, W1Ll, DMODEL, b1_l,
            nullptr, FFDIM, NTOK, DMODEL,
            pTokidx, pTokprob, pSegoff, pCounts, (size_t)FFDIM*DMODEL, FFDIM,
            pHH, pHL, nullptr);
        // FF2: contiguous H rows, prob-weighted atomic scatter into g_Moe
        tgemm_k<2><<<dim3(DMODEL/128, NTOK/128, NEXP), 256, SM_TOT>>>(
            pHH, pHL, FFDIM, W2Hl, W2Ll, FFDIM, b2_l,
            nullptr, DMODEL, NTOK, FFDIM,
            pTokidx, pTokprob, pSegoff, pCounts, (size_t)DMODEL*FFDIM, DMODEL,
            nullptr, nullptr, pMoe);

        add_ln_k<<<NTOK, 256>>>(pX, pMoe, ln2_w + (size_t)l*DMODEL, ln2_b + (size_t)l*DMODEL);
    }

    long auxpos = ((size_t)out_size > TD) ? (long)TD : -1;
    size_t ncopy = ((size_t)out_size > TD) ? TD : (size_t)out_size;
    finalize_k<<<4096, 256>>>(pX, pUsage, out, ncopy, auxpos);
}

// round 6
// speedup vs baseline: 2.4109x; 1.2252x over previous
#include <cuda_runtime.h>
#include <cuda_bf16.h>
#include <math.h>
#include <stdint.h>

#define LAYERS 2
#define DMODEL 1024
#define NHEAD 16
#define HDIM 64
#define FFDIM 4096
#define NEXP 8
#define SEQ 1024
#define BATCH 8
#define NTOK (SEQ*BATCH)          // 8192
#define LNEPS 1e-5f

// ================= persistent scratch =================
__device__ __align__(16) float g_X[(size_t)NTOK*DMODEL];
__device__ __align__(16) float g_QK[(size_t)NTOK*2*DMODEL];
__device__ __align__(16) float g_V[(size_t)NTOK*DMODEL];
__device__ __align__(16) float g_Attn[(size_t)NTOK*DMODEL];
__device__ __align__(16) float g_Moe[(size_t)NTOK*DMODEL];
__device__ int   g_topi[NTOK*2];
__device__ float g_topp[NTOK*2];
__device__ int   g_counts[NEXP];
__device__ int   g_segoff[NEXP];
__device__ int   g_cursor[NEXP];
__device__ int   g_tokidx[2*NTOK];
__device__ float g_tokprob[2*NTOK];
__device__ float g_usage[LAYERS*NEXP];

// bf16 hi/lo splits
__device__ __align__(16) __nv_bfloat16 g_XH[(size_t)NTOK*DMODEL];
__device__ __align__(16) __nv_bfloat16 g_XL[(size_t)NTOK*DMODEL];
__device__ __align__(16) __nv_bfloat16 g_QKinH[(size_t)NTOK*DMODEL];
__device__ __align__(16) __nv_bfloat16 g_QKinL[(size_t)NTOK*DMODEL];
__device__ __align__(16) __nv_bfloat16 g_OH[(size_t)NTOK*DMODEL];
__device__ __align__(16) __nv_bfloat16 g_OL[(size_t)NTOK*DMODEL];
__device__ __align__(16) __nv_bfloat16 g_HH[(size_t)2*NTOK*FFDIM];
__device__ __align__(16) __nv_bfloat16 g_HL[(size_t)2*NTOK*FFDIM];
__device__ __align__(16) __nv_bfloat16 g_WqkvH[(size_t)LAYERS*3*DMODEL*DMODEL];
__device__ __align__(16) __nv_bfloat16 g_WqkvL[(size_t)LAYERS*3*DMODEL*DMODEL];
__device__ __align__(16) __nv_bfloat16 g_WoH[(size_t)LAYERS*DMODEL*DMODEL];
__device__ __align__(16) __nv_bfloat16 g_WoL[(size_t)LAYERS*DMODEL*DMODEL];
__device__ __align__(16) __nv_bfloat16 g_W1H[(size_t)LAYERS*NEXP*FFDIM*DMODEL];
__device__ __align__(16) __nv_bfloat16 g_W1L[(size_t)LAYERS*NEXP*FFDIM*DMODEL];
__device__ __align__(16) __nv_bfloat16 g_W2H[(size_t)LAYERS*NEXP*DMODEL*FFDIM];
__device__ __align__(16) __nv_bfloat16 g_W2L[(size_t)LAYERS*NEXP*DMODEL*FFDIM];

// ================= helpers =================
__device__ __forceinline__ uint32_t s2u(const void* p) {
    uint32_t a;
    asm("{ .reg .u64 t; cvta.to.shared.u64 t, %1; cvt.u32.u64 %0, t; }" : "=r"(a) : "l"(p));
    return a;
}
#define CP_ASYNC(dst, src, sz) \
    asm volatile("cp.async.ca.shared.global [%0], [%1], 16, %2;" :: "r"(dst), "l"(src), "r"(sz))
#define CP_COMMIT() asm volatile("cp.async.commit_group;" ::: "memory")
#define CP_WAIT0()  asm volatile("cp.async.wait_group 0;" ::: "memory")
#define CP_WAIT1()  asm volatile("cp.async.wait_group 1;" ::: "memory")

__device__ __forceinline__ void mma16816(float* c, const uint32_t* a, const uint32_t* b) {
    asm volatile(
        "mma.sync.aligned.m16n8k16.row.col.f32.bf16.bf16.f32 "
        "{%0,%1,%2,%3}, {%4,%5,%6,%7}, {%8,%9}, {%0,%1,%2,%3};"
        : "+f"(c[0]), "+f"(c[1]), "+f"(c[2]), "+f"(c[3])
        : "r"(a[0]), "r"(a[1]), "r"(a[2]), "r"(a[3]), "r"(b[0]), "r"(b[1]));
}
#define LDM4(r0,r1,r2,r3,a) \
    asm volatile("ldmatrix.sync.aligned.m8n8.x4.shared.b16 {%0,%1,%2,%3}, [%4];" \
        : "=r"(r0), "=r"(r1), "=r"(r2), "=r"(r3) : "r"(a))

__device__ __forceinline__ void split2(float v0, float v1, uint32_t& hh, uint32_t& ll) {
    __nv_bfloat16 h0 = __float2bfloat16(v0);
    __nv_bfloat16 h1 = __float2bfloat16(v1);
    __nv_bfloat16 l0 = __float2bfloat16(v0 - __bfloat162float(h0));
    __nv_bfloat16 l1 = __float2bfloat16(v1 - __bfloat162float(h1));
    __nv_bfloat162 ph; ph.x = h0; ph.y = h1;
    __nv_bfloat162 pl; pl.x = l0; pl.y = l1;
    hh = *(uint32_t*)&ph;
    ll = *(uint32_t*)&pl;
}

// smem: 2 stages x [Ah|Al|Bh|Bl], each tile 128 rows x 40 bf16 (padded from 32)
#define LDK 40
#define TILE_B (128*LDK*2)          // 10240
#define OFF_AH 0
#define OFF_AL (1*TILE_B)
#define OFF_BH (2*TILE_B)
#define OFF_BL (3*TILE_B)
#define STG_B  (4*TILE_B)           // 40960
#define SM_AROW (2*STG_B)           // 81920
#define SM_TOT  (SM_AROW + 512)     // 82432

// ================= emulated-fp32 HMMA GEMM =================
// C[128,128 tile] = A[M,K]*B[N,K]^T + bias  via Ah*Bh + Ah*Bl + Al*Bh (bf16 split-3)
// MODE 0: dense fp32 out.
// MODE 1: expert FF1: gather A rows via tokidx, ReLU, split-bf16 out.
// MODE 2: expert FF2: contiguous A rows, prob-weighted atomicAdd scatter to fp32.
template<int MODE>
__global__ __launch_bounds__(256, 2) void tgemm_k(
    const __nv_bfloat16* __restrict__ Ah, const __nv_bfloat16* __restrict__ Al, int lda,
    const __nv_bfloat16* __restrict__ Bh_, const __nv_bfloat16* __restrict__ Bl_, int ldb,
    const float* __restrict__ bias,
    float* __restrict__ C, int ldc,
    int M, int Kd,
    const int* __restrict__ tokidx, const float* __restrict__ tokprob,
    const int* __restrict__ segoff, const int* __restrict__ counts,
    size_t w_stride, int b_stride,
    __nv_bfloat16* __restrict__ HhOut, __nv_bfloat16* __restrict__ HlOut,
    float* __restrict__ scat)
{
    int base = 0;
    const __nv_bfloat16* Bh = Bh_;
    const __nv_bfloat16* Bl = Bl_;
    if (MODE != 0) {
        int e = blockIdx.z;
        base = segoff[e];
        M = counts[e];
        Bh += (size_t)e * w_stride;
        Bl += (size_t)e * w_stride;
        bias += (size_t)e * b_stride;
    }
    int m0 = blockIdx.y * 128;
    if (m0 >= M) return;
    int n0 = blockIdx.x * 128;

    extern __shared__ char smem[];
    uint32_t sbase = s2u(smem);
    int* arow = (int*)(smem + SM_AROW);

    int tid = threadIdx.x;
    int wid = tid >> 5, lid = tid & 31;
    int g8 = lid >> 2, t4 = lid & 3;
    int warpM = wid >> 2, warpN = wid & 3;

    if (tid < 128) {
        int r = m0 + tid;
        int g = -1;
        if (r < M) {
            if (MODE == 1)      g = tokidx[base + r];
            else if (MODE == 2) g = base + r;
            else                g = r;
        }
        arow[tid] = g;
    }
    __syncthreads();

    const int NC = Kd >> 5;   // K chunks of 32

    auto load_stage = [&](int c, int s) {
        int k0 = c << 5;
        uint32_t tb = sbase + s * STG_B;
        #pragma unroll
        for (int i = 0; i < 2; i++) {
            int v  = tid + i * 256;     // 0..511
            int r  = v >> 2;            // 0..127
            int ce = (v & 3) * 8;       // element col (8 bf16 = 16B)
            uint32_t soff = (uint32_t)((r * LDK + ce) * 2);
            int g = arow[r];
            int grow = g >= 0 ? g : 0;
            int sz = g >= 0 ? 16 : 0;
            const char* pah = (const char*)(Ah + (size_t)grow * lda + k0 + ce);
            const char* pal = (const char*)(Al + (size_t)grow * lda + k0 + ce);
            CP_ASYNC(tb + OFF_AH + soff, pah, sz);
            CP_ASYNC(tb + OFF_AL + soff, pal, sz);
            const char* pbh = (const char*)(Bh + (size_t)(n0 + r) * ldb + k0 + ce);
            const char* pbl = (const char*)(Bl + (size_t)(n0 + r) * ldb + k0 + ce);
            CP_ASYNC(tb + OFF_BH + soff, pbh, 16);
            CP_ASYNC(tb + OFF_BL + soff, pbl, 16);
        }
        CP_COMMIT();
    };

    float acc[4][4][4];
    #pragma unroll
    for (int mt = 0; mt < 4; mt++)
        #pragma unroll
        for (int nt = 0; nt < 4; nt++)
            #pragma unroll
            for (int q = 0; q < 4; q++) acc[mt][nt][q] = 0.f;

    // ldmatrix lane-address components
    int lr = lid & 7, quad = lid >> 3;
    // A: mat0=rows0-7/k0-7, mat1=rows8-15/k0-7, mat2=rows0-7/k8-15, mat3=rows8-15/k8-15
    uint32_t aRow = (uint32_t)(warpM * 64 + lr + (quad & 1) * 8);
    uint32_t aK   = (uint32_t)((quad >> 1) * 8);
    // B (per nt-pair p): mat0=n(2p)*8 rows/k0-7, mat1=same rows/k8-15, mat2/3 = nt=2p+1
    uint32_t bRow = (uint32_t)(warpN * 32 + lr + (quad >> 1) * 8);
    uint32_t bK   = (uint32_t)((quad & 1) * 8);

    load_stage(0, 0);

    for (int c = 0; c < NC; c++) {
        int s = c & 1;
        if (c + 1 < NC) { load_stage(c + 1, s ^ 1); CP_WAIT1(); }
        else           { CP_WAIT0(); }
        __syncthreads();

        uint32_t tb = sbase + s * STG_B;
        #pragma unroll
        for (int ks = 0; ks < 2; ks++) {
            uint32_t kb0 = ks * 16;
            uint32_t bh[4][2], bl[4][2];
            #pragma unroll
            for (int p = 0; p < 2; p++) {
                uint32_t baddr = tb + ((bRow + p * 16) * LDK + kb0 + bK) * 2;
                LDM4(bh[2*p][0], bh[2*p][1], bh[2*p+1][0], bh[2*p+1][1], baddr + OFF_BH);
                LDM4(bl[2*p][0], bl[2*p][1], bl[2*p+1][0], bl[2*p+1][1], baddr + OFF_BL);
            }
            #pragma unroll
            for (int mt = 0; mt < 4; mt++) {
                uint32_t aaddr = tb + ((aRow + mt * 16) * LDK + kb0 + aK) * 2;
                uint32_t ah[4], al[4];
                LDM4(ah[0], ah[1], ah[2], ah[3], aaddr + OFF_AH);
                LDM4(al[0], al[1], al[2], al[3], aaddr + OFF_AL);
                #pragma unroll
                for (int nt = 0; nt < 4; nt++) {
                    mma16816(acc[mt][nt], ah, bh[nt]);
                    mma16816(acc[mt][nt], ah, bl[nt]);
                    mma16816(acc[mt][nt], al, bh[nt]);
                }
            }
        }
        __syncthreads();
    }

    // ---------------- epilogue ----------------
    #pragma unroll
    for (int mt = 0; mt < 4; mt++) {
        int r0 = warpM * 64 + mt * 16 + g8;
        #pragma unroll
        for (int half = 0; half < 2; half++) {
            int r = r0 + half * 8;
            if (arow[r] < 0) continue;
            #pragma unroll
            for (int nt = 0; nt < 4; nt++) {
                int gcol = n0 + warpN * 32 + nt * 8 + t4 * 2;
                float v0 = acc[mt][nt][half*2 + 0] + bias[gcol];
                float v1 = acc[mt][nt][half*2 + 1] + bias[gcol + 1];
                if (MODE == 0) {
                    float2 v; v.x = v0; v.y = v1;
                    *(float2*)(C + (size_t)(m0 + r) * ldc + gcol) = v;
                } else if (MODE == 1) {
                    v0 = v0 > 0.f ? v0 : 0.f;
                    v1 = v1 > 0.f ? v1 : 0.f;
                    uint32_t hh, ll;
                    split2(v0, v1, hh, ll);
                    size_t hrow = (size_t)(base + m0 + r) * ldc + gcol;
                    *(uint32_t*)(HhOut + hrow) = hh;
                    *(uint32_t*)(HlOut + hrow) = ll;
                } else {
                    int   tok = tokidx[base + m0 + r];
                    float p   = tokprob[base + m0 + r];
                    float* orow = scat + (size_t)tok * DMODEL + gcol;
                    atomicAdd(orow,     p * v0);
                    atomicAdd(orow + 1, p * v1);
                }
            }
        }
    }
}

// ================= splits / elementwise (vectorized) =================
__global__ void split4_k(const float4* __restrict__ in,
                         uint2* __restrict__ oh, uint2* __restrict__ ol, size_t n4) {
    size_t i = (size_t)blockIdx.x*blockDim.x + threadIdx.x;
    size_t st = (size_t)gridDim.x*blockDim.x;
    for (; i < n4; i += st) {
        float4 v = in[i];
        uint2 H, L;
        split2(v.x, v.y, H.x, L.x);
        split2(v.z, v.w, H.y, L.y);
        oh[i] = H; ol[i] = L;
    }
}
__global__ void addsplit4_k(const float4* __restrict__ a, const float4* __restrict__ b,
                            uint2* __restrict__ oh, uint2* __restrict__ ol, size_t n4) {
    size_t i = (size_t)blockIdx.x*blockDim.x + threadIdx.x;
    size_t st = (size_t)gridDim.x*blockDim.x;
    for (; i < n4; i += st) {
        float4 x = a[i], y = b[i];
        uint2 H, L;
        split2(x.x + y.x, x.y + y.y, H.x, L.x);
        split2(x.z + y.z, x.w + y.w, H.y, L.y);
        oh[i] = H; ol[i] = L;
    }
}
// copy src into X AND emit bf16 split
__global__ void splitcopy4_k(const float4* __restrict__ in, float4* __restrict__ o,
                             uint2* __restrict__ oh, uint2* __restrict__ ol, size_t n4) {
    size_t i = (size_t)blockIdx.x*blockDim.x + threadIdx.x;
    size_t st = (size_t)gridDim.x*blockDim.x;
    for (; i < n4; i += st) {
        float4 v = in[i];
        o[i] = v;
        uint2 H, L;
        split2(v.x, v.y, H.x, L.x);
        split2(v.z, v.w, H.y, L.y);
        oh[i] = H; ol[i] = L;
    }
}
__global__ void zero_k(float* __restrict__ p, size_t n, int* a, int* b, int nc) {
    size_t i = (size_t)blockIdx.x*blockDim.x + threadIdx.x;
    size_t st = (size_t)gridDim.x*blockDim.x;
    for (; i < n; i += st) p[i] = 0.f;
    if (blockIdx.x == 0 && (int)threadIdx.x < nc) {
        if (a) a[threadIdx.x] = 0;
        if (b) b[threadIdx.x] = 0;
    }
}

// ================= flash attention (epilogue -> bf16 split O) =================
#define SP 65
#define FLASH_SMEM ((4*64*SP + 64*17) * 4)

__global__ __launch_bounds__(256) void flash_k(const float* __restrict__ QK,
                                               const float* __restrict__ V,
                                               __nv_bfloat16* __restrict__ OH,
                                               __nv_bfloat16* __restrict__ OL)
{
    extern __shared__ float sm[];
    float* Qs  = sm;
    float* Ks  = Qs + 64*SP;
    float* Vs  = Ks + 64*SP;
    float* Ps  = Vs + 64*SP;
    float* red = Ps + 64*SP;

    int tid = threadIdx.x;
    int tx = tid & 15, ty = tid >> 4;
    int bh = blockIdx.y;
    int b  = bh >> 4;
    int h  = bh & 15;
    int s0 = blockIdx.x * 64;

    #pragma unroll
    for (int i = 0; i < 4; i++) {
        int r = ty + i*16;
        int d = tx * 4;
        float4 q = *(const float4*)(QK + ((size_t)((s0+r)*BATCH + b))*2048 + h*64 + d);
        Qs[r*SP + d]   = q.x; Qs[r*SP + d+1] = q.y;
        Qs[r*SP + d+2] = q.z; Qs[r*SP + d+3] = q.w;
    }

    float m_i[4], l_i[4], o_acc[4][4];
    #pragma unroll
    for (int i = 0; i < 4; i++) {
        m_i[i] = -1e30f; l_i[i] = 0.f;
        #pragma unroll
        for (int j = 0; j < 4; j++) o_acc[i][j] = 0.f;
    }
    const float scale = 0.125f;

    for (int t0 = 0; t0 < SEQ; t0 += 64) {
        __syncthreads();
        #pragma unroll
        for (int i = 0; i < 4; i++) {
            int r = ty + i*16;
            int d = tx * 4;
            size_t tok = (size_t)((t0+r)*BATCH + b);
            float4 kv = *(const float4*)(QK + tok*2048 + DMODEL + h*64 + d);
            Ks[r*SP + d]   = kv.x; Ks[r*SP + d+1] = kv.y;
            Ks[r*SP + d+2] = kv.z; Ks[r*SP + d+3] = kv.w;
            float4 vv = *(const float4*)(V + tok*DMODEL + h*64 + d);
            Vs[r*SP + d]   = vv.x; Vs[r*SP + d+1] = vv.y;
            Vs[r*SP + d+2] = vv.z; Vs[r*SP + d+3] = vv.w;
        }
        __syncthreads();

        float s[4][4];
        #pragma unroll
        for (int i = 0; i < 4; i++)
            #pragma unroll
            for (int j = 0; j < 4; j++) s[i][j] = 0.f;
        for (int d = 0; d < 64; d++) {
            float a0 = Qs[(ty*4+0)*SP + d], a1 = Qs[(ty*4+1)*SP + d];
            float a2 = Qs[(ty*4+2)*SP + d], a3 = Qs[(ty*4+3)*SP + d];
            float b0 = Ks[(tx*4+0)*SP + d], b1 = Ks[(tx*4+1)*SP + d];
            float b2 = Ks[(tx*4+2)*SP + d], b3 = Ks[(tx*4+3)*SP + d];
            s[0][0]+=a0*b0; s[0][1]+=a0*b1; s[0][2]+=a0*b2; s[0][3]+=a0*b3;
            s[1][0]+=a1*b0; s[1][1]+=a1*b1; s[1][2]+=a1*b2; s[1][3]+=a1*b3;
            s[2][0]+=a2*b0; s[2][1]+=a2*b1; s[2][2]+=a2*b2; s[2][3]+=a2*b3;
            s[3][0]+=a3*b0; s[3][1]+=a3*b1; s[3][2]+=a3*b2; s[3][3]+=a3*b3;
        }
        #pragma unroll
        for (int i = 0; i < 4; i++)
            #pragma unroll
            for (int j = 0; j < 4; j++) s[i][j] *= scale;

        #pragma unroll
        for (int i = 0; i < 4; i++) {
            float mx = fmaxf(fmaxf(s[i][0], s[i][1]), fmaxf(s[i][2], s[i][3]));
            red[(ty*4+i)*17 + tx] = mx;
        }
        __syncthreads();

        float p[4][4], lsum[4], alpha[4];
        #pragma unroll
        for (int i = 0; i < 4; i++) {
            int r = ty*4 + i;
            float rm = red[r*17 + 0];
            #pragma unroll
            for (int k = 1; k < 16; k++) rm = fmaxf(rm, red[r*17 + k]);
            float nm = fmaxf(m_i[i], rm);
            alpha[i] = __expf(m_i[i] - nm);
            m_i[i] = nm;
            float ls = 0.f;
            #pragma unroll
            for (int j = 0; j < 4; j++) { p[i][j] = __expf(s[i][j] - nm); ls += p[i][j]; }
            lsum[i] = ls;
            #pragma unroll
            for (int j = 0; j < 4; j++) o_acc[i][j] *= alpha[i];
        }
        __syncthreads();
        #pragma unroll
        for (int i = 0; i < 4; i++) {
            red[(ty*4+i)*17 + tx] = lsum[i];
            #pragma unroll
            for (int j = 0; j < 4; j++) Ps[(ty*4+i)*SP + tx*4 + j] = p[i][j];
        }
        __syncthreads();
        #pragma unroll
        for (int i = 0; i < 4; i++) {
            int r = ty*4 + i;
            float rs = 0.f;
            #pragma unroll
            for (int k = 0; k < 16; k++) rs += red[r*17 + k];
            l_i[i] = l_i[i]*alpha[i] + rs;
        }
        for (int c = 0; c < 64; c++) {
            float p0 = Ps[(ty*4+0)*SP + c], p1 = Ps[(ty*4+1)*SP + c];
            float p2 = Ps[(ty*4+2)*SP + c], p3 = Ps[(ty*4+3)*SP + c];
            float v0 = Vs[c*SP + tx*4+0], v1 = Vs[c*SP + tx*4+1];
            float v2 = Vs[c*SP + tx*4+2], v3 = Vs[c*SP + tx*4+3];
            o_acc[0][0]+=p0*v0; o_acc[0][1]+=p0*v1; o_acc[0][2]+=p0*v2; o_acc[0][3]+=p0*v3;
            o_acc[1][0]+=p1*v0; o_acc[1][1]+=p1*v1; o_acc[1][2]+=p1*v2; o_acc[1][3]+=p1*v3;
            o_acc[2][0]+=p2*v0; o_acc[2][1]+=p2*v1; o_acc[2][2]+=p2*v2; o_acc[2][3]+=p2*v3;
            o_acc[3][0]+=p3*v0; o_acc[3][1]+=p3*v1; o_acc[3][2]+=p3*v2; o_acc[3][3]+=p3*v3;
        }
    }

    #pragma unroll
    for (int i = 0; i < 4; i++) {
        float inv = 1.f / l_i[i];
        size_t row = (size_t)((s0 + ty*4 + i)*BATCH + b)*DMODEL + h*64 + tx*4;
        uint32_t H0, L0, H1, L1;
        split2(o_acc[i][0]*inv, o_acc[i][1]*inv, H0, L0);
        split2(o_acc[i][2]*inv, o_acc[i][3]*inv, H1, L1);
        *(uint32_t*)(OH + row)     = H0;
        *(uint32_t*)(OH + row + 2) = H1;
        *(uint32_t*)(OL + row)     = L0;
        *(uint32_t*)(OL + row + 2) = L1;
    }
}

// ================= residual + layernorm (emits fp32 X AND bf16 split) =================
__global__ __launch_bounds__(256) void add_ln_k(float* __restrict__ X,
                                                const float* __restrict__ R,
                                                const float* __restrict__ w,
                                                const float* __restrict__ b,
                                                __nv_bfloat16* __restrict__ XH,
                                                __nv_bfloat16* __restrict__ XL)
{
    int t = blockIdx.x;
    size_t off = (size_t)t*DMODEL + threadIdx.x*4;
    float4 xv = *(const float4*)(X + off);
    float4 rv = *(const float4*)(R + off);
    float v0 = xv.x + rv.x, v1 = xv.y + rv.y, v2 = xv.z + rv.z, v3 = xv.w + rv.w;
    float s  = v0+v1+v2+v3;
    float sq = v0*v0+v1*v1+v2*v2+v3*v3;

    __shared__ float ssum[8], ssq[8];
    __shared__ float s_mean, s_rstd;
    int lane = threadIdx.x & 31, wp = threadIdx.x >> 5;
    #pragma unroll
    for (int o = 16; o; o >>= 1) {
        s  += __shfl_xor_sync(0xffffffff, s, o);
        sq += __shfl_xor_sync(0xffffffff, sq, o);
    }
    if (lane == 0) { ssum[wp] = s; ssq[wp] = sq; }
    __syncthreads();
    if (threadIdx.x == 0) {
        float S = 0.f, Q = 0.f;
        #pragma unroll
        for (int k = 0; k < 8; k++) { S += ssum[k]; Q += ssq[k]; }
        float mean = S * (1.f/DMODEL);
        float var  = Q * (1.f/DMODEL) - mean*mean;
        s_mean = mean;
        s_rstd = rsqrtf(var + LNEPS);
    }
    __syncthreads();
    float mean = s_mean, rs = s_rstd;
    int c = threadIdx.x*4;
    float4 out;
    out.x = (v0-mean)*rs*w[c+0] + b[c+0];
    out.y = (v1-mean)*rs*w[c+1] + b[c+1];
    out.z = (v2-mean)*rs*w[c+2] + b[c+2];
    out.w = (v3-mean)*rs*w[c+3] + b[c+3];
    *(float4*)(X + off) = out;
    uint2 H, L;
    split2(out.x, out.y, H.x, L.x);
    split2(out.z, out.w, H.y, L.y);
    *(uint2*)(XH + off) = H;
    *(uint2*)(XL + off) = L;
}

// ================= MoE gate =================
__global__ __launch_bounds__(256) void gate_k(const float* __restrict__ X,
                                              const float* __restrict__ gw,
                                              const float* __restrict__ gb,
                                              int* __restrict__ topi, float* __restrict__ topp,
                                              int* __restrict__ counts, float* __restrict__ usage)
{
    int wp = threadIdx.x >> 5, lane = threadIdx.x & 31;
    int t = blockIdx.x * 8 + wp;
    const float* xr = X + (size_t)t*DMODEL;
    float acc[NEXP];
    #pragma unroll
    for (int e = 0; e < NEXP; e++) acc[e] = 0.f;
    for (int d = lane; d < DMODEL; d += 32) {
        float xv = xr[d];
        #pragma unroll
        for (int e = 0; e < NEXP; e++) acc[e] += xv * gw[e*DMODEL + d];
    }
    #pragma unroll
    for (int e = 0; e < NEXP; e++)
        #pragma unroll
        for (int o = 16; o; o >>= 1) acc[e] += __shfl_down_sync(0xffffffff, acc[e], o);
    if (lane == 0) {
        float sc[NEXP];
        #pragma unroll
        for (int e = 0; e < NEXP; e++) sc[e] = acc[e] + gb[e];
        int i1 = 0;
        #pragma unroll
        for (int e = 1; e < NEXP; e++) if (sc[e] > sc[i1]) i1 = e;
        int i2 = -1;
        #pragma unroll
        for (int e = 0; e < NEXP; e++) if (e != i1 && (i2 < 0 || sc[e] > sc[i2])) i2 = e;
        float e2 = __expf(sc[i2] - sc[i1]);
        float inv = 1.f / (1.f + e2);
        float p1 = inv, p2 = e2 * inv;
        topi[2*t] = i1; topi[2*t+1] = i2;
        topp[2*t] = p1; topp[2*t+1] = p2;
        atomicAdd(&counts[i1], 1); atomicAdd(&counts[i2], 1);
        atomicAdd(&usage[i1], p1); atomicAdd(&usage[i2], p2);
    }
}

__global__ void scan_k(const int* __restrict__ counts, int* __restrict__ segoff) {
    if (threadIdx.x == 0) {
        int run = 0;
        for (int e = 0; e < NEXP; e++) { segoff[e] = run; run += counts[e]; }
    }
}

__global__ void fill_k(const int* __restrict__ topi, const float* __restrict__ topp,
                       const int* __restrict__ segoff, int* __restrict__ cursor,
                       int* __restrict__ tokidx, float* __restrict__ tokprob)
{
    int t = blockIdx.x*256 + threadIdx.x;
    #pragma unroll
    for (int j = 0; j < 2; j++) {
        int e = topi[2*t + j];
        int slot = atomicAdd(&cursor[e], 1);
        int p = segoff[e] + slot;
        tokidx[p] = t;
        tokprob[p] = topp[2*t + j];
    }
}

// ================= finalize =================
__global__ void finalize_k(const float* __restrict__ X, const float* __restrict__ usage,
                           float* __restrict__ out, size_t n, long auxpos)
{
    size_t i = (size_t)blockIdx.x*blockDim.x + threadIdx.x;
    size_t st = (size_t)gridDim.x*blockDim.x;
    for (; i < n; i += st) out[i] = X[i];
    if (blockIdx.x == 0 && threadIdx.x == 0 && auxpos >= 0) {
        float aux = 0.f;
        for (int l = 0; l < LAYERS; l++) {
            float sum = 0.f;
            for (int e = 0; e < NEXP; e++) sum += usage[l*NEXP + e];
            float ent = 0.f;
            for (int e = 0; e < NEXP; e++) {
                float p = usage[l*NEXP + e] / sum;
                ent -= p * logf(p + 1e-9f);
            }
            aux += ent * (1.f / LAYERS);
        }
        out[auxpos] = aux;
    }
}

// ================= host orchestration =================
extern "C" void kernel_launch(void* const* d_in, const int* in_sizes, int n_in,
                              void* d_out, int out_size)
{
    (void)in_sizes; (void)n_in;
    const float* src    = (const float*)d_in[0];
    const float* pos    = (const float*)d_in[1];
    const float* qkv_w  = (const float*)d_in[2];
    const float* qkv_b  = (const float*)d_in[3];
    const float* out_w  = (const float*)d_in[4];
    const float* out_b  = (const float*)d_in[5];
    const float* ln1_w  = (const float*)d_in[6];
    const float* ln1_b  = (const float*)d_in[7];
    const float* ln2_w  = (const float*)d_in[8];
    const float* ln2_b  = (const float*)d_in[9];
    const float* gate_w = (const float*)d_in[10];
    const float* gate_b = (const float*)d_in[11];
    const float* w1     = (const float*)d_in[12];
    const float* b1     = (const float*)d_in[13];
    const float* w2     = (const float*)d_in[14];
    const float* b2     = (const float*)d_in[15];
    float* out = (float*)d_out;

    float *pX, *pQK, *pV, *pAttn, *pMoe, *pTopp, *pTokprob, *pUsage;
    int *pTopi, *pCounts, *pSegoff, *pCursor, *pTokidx;
    __nv_bfloat16 *pXH, *pXL, *pQKinH, *pQKinL, *pOH, *pOL, *pHH, *pHL;
    __nv_bfloat16 *pWqkvH, *pWqkvL, *pWoH, *pWoL, *pW1H, *pW1L, *pW2H, *pW2L;

    cudaGetSymbolAddress((void**)&pX, g_X);
    cudaGetSymbolAddress((void**)&pQK, g_QK);
    cudaGetSymbolAddress((void**)&pV, g_V);
    cudaGetSymbolAddress((void**)&pAttn, g_Attn);
    cudaGetSymbolAddress((void**)&pMoe, g_Moe);
    cudaGetSymbolAddress((void**)&pTopi, g_topi);
    cudaGetSymbolAddress((void**)&pTopp, g_topp);
    cudaGetSymbolAddress((void**)&pCounts, g_counts);
    cudaGetSymbolAddress((void**)&pSegoff, g_segoff);
    cudaGetSymbolAddress((void**)&pCursor, g_cursor);
    cudaGetSymbolAddress((void**)&pTokidx, g_tokidx);
    cudaGetSymbolAddress((void**)&pTokprob, g_tokprob);
    cudaGetSymbolAddress((void**)&pUsage, g_usage);
    cudaGetSymbolAddress((void**)&pXH, g_XH);
    cudaGetSymbolAddress((void**)&pXL, g_XL);
    cudaGetSymbolAddress((void**)&pQKinH, g_QKinH);
    cudaGetSymbolAddress((void**)&pQKinL, g_QKinL);
    cudaGetSymbolAddress((void**)&pOH, g_OH);
    cudaGetSymbolAddress((void**)&pOL, g_OL);
    cudaGetSymbolAddress((void**)&pHH, g_HH);
    cudaGetSymbolAddress((void**)&pHL, g_HL);
    cudaGetSymbolAddress((void**)&pWqkvH, g_WqkvH);
    cudaGetSymbolAddress((void**)&pWqkvL, g_WqkvL);
    cudaGetSymbolAddress((void**)&pWoH, g_WoH);
    cudaGetSymbolAddress((void**)&pWoL, g_WoL);
    cudaGetSymbolAddress((void**)&pW1H, g_W1H);
    cudaGetSymbolAddress((void**)&pW1L, g_W1L);
    cudaGetSymbolAddress((void**)&pW2H, g_W2H);
    cudaGetSymbolAddress((void**)&pW2L, g_W2L);

    cudaFuncSetAttribute(flash_k, cudaFuncAttributeMaxDynamicSharedMemorySize, 72*1024);
    cudaFuncSetAttribute(tgemm_k<0>, cudaFuncAttributeMaxDynamicSharedMemorySize, SM_TOT);
    cudaFuncSetAttribute(tgemm_k<1>, cudaFuncAttributeMaxDynamicSharedMemorySize, SM_TOT);
    cudaFuncSetAttribute(tgemm_k<2>, cudaFuncAttributeMaxDynamicSharedMemorySize, SM_TOT);

    const size_t TD = (size_t)NTOK * DMODEL;

    // split all weights to bf16 hi/lo (deterministic, every launch)
    split4_k<<<4096, 256>>>((const float4*)qkv_w, (uint2*)pWqkvH, (uint2*)pWqkvL, (size_t)LAYERS*3*DMODEL*DMODEL/4);
    split4_k<<<4096, 256>>>((const float4*)out_w, (uint2*)pWoH,  (uint2*)pWoL,  (size_t)LAYERS*DMODEL*DMODEL/4);
    split4_k<<<8192, 256>>>((const float4*)w1,    (uint2*)pW1H,  (uint2*)pW1L,  (size_t)LAYERS*NEXP*FFDIM*DMODEL/4);
    split4_k<<<8192, 256>>>((const float4*)w2,    (uint2*)pW2H,  (uint2*)pW2L,  (size_t)LAYERS*NEXP*DMODEL*FFDIM/4);

    splitcopy4_k<<<4096, 256>>>((const float4*)src, (float4*)pX, (uint2*)pXH, (uint2*)pXL, TD/4);
    zero_k<<<1, 64>>>(pUsage, LAYERS*NEXP, nullptr, nullptr, 0);

    for (int l = 0; l < LAYERS; l++) {
        const float* qkvb_l = qkv_b + (size_t)l*3*DMODEL;
        const float* outb_l = out_b + (size_t)l*DMODEL;
        const float* gw_l   = gate_w + (size_t)l*NEXP*DMODEL;
        const float* gb_l   = gate_b + (size_t)l*NEXP;
        const float* b1_l   = b1 + (size_t)l*NEXP*FFDIM;
        const float* b2_l   = b2 + (size_t)l*NEXP*DMODEL;
        const __nv_bfloat16* WqH = pWqkvH + (size_t)l*3*DMODEL*DMODEL;
        const __nv_bfloat16* WqL = pWqkvL + (size_t)l*3*DMODEL*DMODEL;
        const __nv_bfloat16* WoHl = pWoH + (size_t)l*DMODEL*DMODEL;
        const __nv_bfloat16* WoLl = pWoL + (size_t)l*DMODEL*DMODEL;
        const __nv_bfloat16* W1Hl = pW1H + (size_t)l*NEXP*FFDIM*DMODEL;
        const __nv_bfloat16* W1Ll = pW1L + (size_t)l*NEXP*FFDIM*DMODEL;
        const __nv_bfloat16* W2Hl = pW2H + (size_t)l*NEXP*DMODEL*FFDIM;
        const __nv_bfloat16* W2Ll = pW2L + (size_t)l*NEXP*DMODEL*FFDIM;

        // QKin = X + pos (split); XH/XL already current (from splitcopy / prev LN2)
        addsplit4_k<<<4096, 256>>>((const float4*)pX, (const float4*)pos,
                                   (uint2*)pQKinH, (uint2*)pQKinL, TD/4);

        // Q|K fused GEMM -> g_QK [T,2048]
        tgemm_k<0><<<dim3(16, 64), 256, SM_TOT>>>(
            pQKinH, pQKinL, DMODEL, WqH, WqL, DMODEL, qkvb_l,
            pQK, 2*DMODEL, NTOK, DMODEL,
            nullptr, nullptr, nullptr, nullptr, 0, 0, nullptr, nullptr, nullptr);
        // V GEMM -> g_V
        tgemm_k<0><<<dim3(8, 64), 256, SM_TOT>>>(
            pXH, pXL, DMODEL, WqH + (size_t)2*DMODEL*DMODEL, WqL + (size_t)2*DMODEL*DMODEL, DMODEL,
            qkvb_l + 2*DMODEL, pV, DMODEL, NTOK, DMODEL,
            nullptr, nullptr, nullptr, nullptr, 0, 0, nullptr, nullptr, nullptr);

        // flash attention -> OH/OL (bf16 split, no fp32 O)
        flash_k<<<dim3(16, 128), 256, FLASH_SMEM>>>(pQK, pV, pOH, pOL);

        // output projection -> g_Attn
        tgemm_k<0><<<dim3(8, 64), 256, SM_TOT>>>(
            pOH, pOL, DMODEL, WoHl, WoLl, DMODEL, outb_l,
            pAttn, DMODEL, NTOK, DMODEL,
            nullptr, nullptr, nullptr, nullptr, 0, 0, nullptr, nullptr, nullptr);

        // X = LN(X + attn); also emits XH/XL (A for FF1)
        add_ln_k<<<NTOK, 256>>>(pX, pAttn, ln1_w + (size_t)l*DMODEL, ln1_b + (size_t)l*DMODEL,
                                pXH, pXL);

        // MoE routing
        zero_k<<<4096, 256>>>(pMoe, TD, pCounts, pCursor, NEXP);
        gate_k<<<NTOK/8, 256>>>(pX, gw_l, gb_l, pTopi, pTopp, pCounts, pUsage + l*NEXP);
        scan_k<<<1, 32>>>(pCounts, pSegoff);
        fill_k<<<NTOK/256, 256>>>(pTopi, pTopp, pSegoff, pCursor, pTokidx, pTokprob);

        // FF1: gather rows of X, ReLU, write split-bf16 H
        tgemm_k<1><<<dim3(FFDIM/128, NTOK/128, NEXP), 256, SM_TOT>>>(
            pXH, pXL, DMODEL, W1Hl, W1Ll, DMODEL, b1_l,
            nullptr, FFDIM, NTOK, DMODEL,
            pTokidx, pTokprob, pSegoff, pCounts, (size_t)FFDIM*DMODEL, FFDIM,
            pHH, pHL, nullptr);
        // FF2: contiguous H rows, prob-weighted atomic scatter into g_Moe
        tgemm_k<2><<<dim3(DMODEL/128, NTOK/128, NEXP), 256, SM_TOT>>>(
            pHH, pHL, FFDIM, W2Hl, W2Ll, FFDIM, b2_l,
            nullptr, DMODEL, NTOK, FFDIM,
            pTokidx, pTokprob, pSegoff, pCounts, (size_t)DMODEL*FFDIM, DMODEL,
            nullptr, nullptr, pMoe);

        // X = LN(X + moe); also emits XH/XL (A for next layer's V GEMM)
        add_ln_k<<<NTOK, 256>>>(pX, pMoe, ln2_w + (size_t)l*DMODEL, ln2_b + (size_t)l*DMODEL,
                                pXH, pXL);
    }

    long auxpos = ((size_t)out_size > TD) ? (long)TD : -1;
    size_t ncopy = ((size_t)out_size > TD) ? TD : (size_t)out_size;
    finalize_k<<<4096, 256>>>(pX, pUsage, out, ncopy, auxpos);
}